// round 1
// baseline (speedup 1.0000x reference)
#include <cuda_runtime.h>

// ---------------- problem constants ----------------
#define BB   4
#define SS   1024
#define WW   8
#define DIMC 64
#define HH   4
#define HD   128          // head dim = W*DIM/H

// ---------------- device scratch ----------------
__device__ float g_svec[DIMC];
__device__ float g_q[BB*HH*SS*HD];
__device__ float g_k[BB*HH*SS*HD];
__device__ float g_v[BB*HH*SS*HD];
__device__ float g_nega[BB*HH*SS];   // -(ph @ head_w^T)  per (b,h,t)
__device__ float g_pv[BB*HH*HD];     // pos_attn @ v  (row-constant)

// ---------------- K0: strength projection ----------------
__global__ void k_svec(const float* __restrict__ strength,
                       const float* __restrict__ str_w,
                       const float* __restrict__ str_b) {
    int d = threadIdx.x;            // 64 threads
    float s = 0.f;
    #pragma unroll 8
    for (int i = 0; i < 512; i++) s += str_w[d*512 + i] * strength[i];
    g_svec[d] = s + str_b[d];
}

// ---------------- K1: q/k/v projections ----------------
// y[b,s,w,d] = sum_c x[b,c,s,w] * E[d,c] + svec[d], for E in {qe,ke,ve}
// stored as [b][h][s][j] with h=w>>1, j=((w&1)<<6)|d
__global__ __launch_bounds__(256) void k_proj(
    const float* __restrict__ x,
    const float* __restrict__ qw, const float* __restrict__ kw,
    const float* __restrict__ vw, const int* __restrict__ embid)
{
    extern __shared__ float sm[];
    float* xT = sm;               // [64 c][68] cols m = s_local*8+w (64 rows of x per CTA = 8 s)
    float* qT = sm + 64*68;       // [64 c][68] cols d
    float* kT = qT + 64*68;
    float* vT = kT + 64*68;

    const int sblk = blockIdx.x;          // 128 s-blocks of 8
    const int b    = blockIdx.y;
    const int s0   = sblk * 8;
    const int tid  = threadIdx.x;
    const int id   = embid[0];
    const float* qwb = qw + (size_t)id * 4096;
    const float* kwb = kw + (size_t)id * 4096;
    const float* vwb = vw + (size_t)id * 4096;

    for (int i = tid; i < 4096; i += 256) {
        // x tile: coalesced 64-float rows
        int c = i >> 6, m = i & 63;
        int sl = m >> 3, w = m & 7;
        xT[c*68 + m] = x[(((size_t)b*64 + c)*1024 + (s0 + sl))*8 + w];
        // emb: coalesced read, transposed store
        int d2 = i >> 6, c2 = i & 63;
        qT[c2*68 + d2] = qwb[d2*64 + c2];
        kT[c2*68 + d2] = kwb[d2*64 + c2];
        vT[c2*68 + d2] = vwb[d2*64 + c2];
    }
    __syncthreads();

    const int tx = tid & 15, ty = tid >> 4;
    float aq[4][4] = {}, ak[4][4] = {}, av[4][4] = {};
    #pragma unroll 4
    for (int c = 0; c < 64; c++) {
        float4 xf = *(const float4*)&xT[c*68 + ty*4];
        float4 qf = *(const float4*)&qT[c*68 + tx*4];
        float4 kf = *(const float4*)&kT[c*68 + tx*4];
        float4 vf = *(const float4*)&vT[c*68 + tx*4];
        float xr[4] = {xf.x, xf.y, xf.z, xf.w};
        float qr[4] = {qf.x, qf.y, qf.z, qf.w};
        float kr[4] = {kf.x, kf.y, kf.z, kf.w};
        float vr[4] = {vf.x, vf.y, vf.z, vf.w};
        #pragma unroll
        for (int i = 0; i < 4; i++)
            #pragma unroll
            for (int j = 0; j < 4; j++) {
                aq[i][j] += xr[i] * qr[j];
                ak[i][j] += xr[i] * kr[j];
                av[i][j] += xr[i] * vr[j];
            }
    }

    float sv[4];
    #pragma unroll
    for (int j = 0; j < 4; j++) sv[j] = g_svec[tx*4 + j];

    #pragma unroll
    for (int i = 0; i < 4; i++) {
        int m = ty*4 + i;
        int sl = m >> 3, w = m & 7;
        int h = w >> 1;
        int jb = ((w & 1) << 6) + tx*4;
        size_t base = (((size_t)(b*4 + h)*1024 + (s0 + sl))*128 + jb);
        float4 o;
        o.x = aq[i][0]+sv[0]; o.y = aq[i][1]+sv[1]; o.z = aq[i][2]+sv[2]; o.w = aq[i][3]+sv[3];
        *(float4*)&g_q[base] = o;
        o.x = ak[i][0]+sv[0]; o.y = ak[i][1]+sv[1]; o.z = ak[i][2]+sv[2]; o.w = ak[i][3]+sv[3];
        *(float4*)&g_k[base] = o;
        o.x = av[i][0]+sv[0]; o.y = av[i][1]+sv[1]; o.z = av[i][2]+sv[2]; o.w = av[i][3]+sv[3];
        *(float4*)&g_v[base] = o;
    }
}

// ---------------- K2a: positional MLP (collapsed) ----------------
__global__ void k_pos(const float* __restrict__ pos,
                      const float* __restrict__ w1, const float* __restrict__ b1,
                      const float* __restrict__ w2, const float* __restrict__ b2,
                      const float* __restrict__ hw)
{
    int idx = blockIdx.x * blockDim.x + threadIdx.x;   // b*1024 + s
    if (idx >= BB*SS) return;
    float p0 = pos[idx*3+0], p1 = pos[idx*3+1], p2 = pos[idx*3+2];
    float h1[3];
    #pragma unroll
    for (int j = 0; j < 3; j++)
        h1[j] = fmaxf(0.f, w1[j*3+0]*p0 + w1[j*3+1]*p1 + w1[j*3+2]*p2 + b1[j]);
    float ph[8];
    #pragma unroll
    for (int d = 0; d < 8; d++)
        ph[d] = w2[d*3+0]*h1[0] + w2[d*3+1]*h1[1] + w2[d*3+2]*h1[2] + b2[d];
    int b = idx >> 10, s = idx & 1023;
    #pragma unroll
    for (int h = 0; h < 4; h++) {
        float a = 0.f;
        #pragma unroll
        for (int d = 0; d < 8; d++) a += ph[d] * hw[h*8 + d];
        g_nega[((size_t)(b*4 + h))*1024 + s] = -a;   // head_b cancels in softmax
    }
}

// ---------------- K2b: pv = softmax(-a) @ V  per (b,h) ----------------
__global__ void k_pv() {
    __shared__ float sp[1024];
    __shared__ float red[128];
    int bh = blockIdx.x, tid = threadIdx.x;   // 128 threads
    const float* na = g_nega + (size_t)bh*1024;

    float mx = -1e30f;
    for (int t = tid; t < 1024; t += 128) mx = fmaxf(mx, na[t]);
    red[tid] = mx; __syncthreads();
    for (int s = 64; s > 0; s >>= 1) { if (tid < s) red[tid] = fmaxf(red[tid], red[tid+s]); __syncthreads(); }
    mx = red[0]; __syncthreads();

    float sum = 0.f;
    for (int t = tid; t < 1024; t += 128) { float e = __expf(na[t] - mx); sp[t] = e; sum += e; }
    red[tid] = sum; __syncthreads();
    for (int s = 64; s > 0; s >>= 1) { if (tid < s) red[tid] += red[tid+s]; __syncthreads(); }
    float inv = 1.f / red[0];
    __syncthreads();

    const float* v = g_v + (size_t)bh*1024*128;
    float acc = 0.f;
    #pragma unroll 4
    for (int t = 0; t < 1024; t++) acc += sp[t] * v[(size_t)t*128 + tid];
    g_pv[bh*128 + tid] = acc * inv;
}

// ---------------- K3: flash attention + gate combine + out_w GEMM ----------------
// grid (16 s-tiles, 16 bh), 256 threads (16x16), each thread 4x4 register tiles
__global__ __launch_bounds__(256) void k_attn(
    const float* __restrict__ gate, const float* __restrict__ out_w,
    const float* __restrict__ out_b, float* __restrict__ out)
{
    extern __shared__ float sm[];
    float* qT  = sm;              // [128 kk][68]  (q * scale, transposed)
    float* kT  = sm + 8704;       // [128 kk][68]
    float* sV  = sm + 17408;      // [64 t][128 d]
    float* sPT = sm + 25600;      // [64 t][68 r]
    // epilogue reuse: oT = sm (128x68), owT = sm+25600 (64x68)

    const int stile = blockIdx.x, bh = blockIdx.y;
    const int b = bh >> 2, h = bh & 3;
    const int s0 = stile * 64;
    const int tid = threadIdx.x, tx = tid & 15, ty = tid >> 4;

    const float* Q = g_q + (size_t)bh*1024*128;
    const float* K = g_k + (size_t)bh*1024*128;
    const float* V = g_v + (size_t)bh*1024*128;
    const float scale = 0.08838834764831845f;   // 1/sqrt(128)

    // Q tile, transposed + pre-scaled
    for (int i = tid; i < 64*128; i += 256) {
        int r = i >> 7, kk = i & 127;
        qT[kk*68 + r] = Q[(size_t)(s0 + r)*128 + kk] * scale;
    }

    float m[4], l[4], o[4][8];
    #pragma unroll
    for (int i = 0; i < 4; i++) {
        m[i] = -1e30f; l[i] = 0.f;
        #pragma unroll
        for (int j = 0; j < 8; j++) o[i][j] = 0.f;
    }

    for (int t0 = 0; t0 < 1024; t0 += 64) {
        __syncthreads();
        for (int i = tid; i < 64*128; i += 256) {
            int c = i >> 7, kk = i & 127;
            kT[kk*68 + c] = K[(size_t)(t0 + c)*128 + kk];
            sV[i] = V[(size_t)t0*128 + i];
        }
        __syncthreads();

        // S = Qs @ K^T (64x64), 4x4 per thread
        float acc[4][4] = {};
        #pragma unroll 2
        for (int kk = 0; kk < 128; kk++) {
            float4 qf = *(const float4*)&qT[kk*68 + ty*4];
            float4 kf = *(const float4*)&kT[kk*68 + tx*4];
            float qr[4] = {qf.x, qf.y, qf.z, qf.w};
            float kr[4] = {kf.x, kf.y, kf.z, kf.w};
            #pragma unroll
            for (int i = 0; i < 4; i++)
                #pragma unroll
                for (int j = 0; j < 4; j++) acc[i][j] += qr[i] * kr[j];
        }

        // online softmax (row reductions across tx = half-warp shuffles)
        #pragma unroll
        for (int i = 0; i < 4; i++) {
            float tm = fmaxf(fmaxf(acc[i][0], acc[i][1]), fmaxf(acc[i][2], acc[i][3]));
            #pragma unroll
            for (int ofs = 1; ofs < 16; ofs <<= 1)
                tm = fmaxf(tm, __shfl_xor_sync(0xffffffffu, tm, ofs));
            float mn  = fmaxf(m[i], tm);
            float fac = __expf(m[i] - mn);
            m[i] = mn;
            float rs = 0.f;
            #pragma unroll
            for (int j = 0; j < 4; j++) { acc[i][j] = __expf(acc[i][j] - mn); rs += acc[i][j]; }
            #pragma unroll
            for (int ofs = 1; ofs < 16; ofs <<= 1)
                rs += __shfl_xor_sync(0xffffffffu, rs, ofs);
            l[i] = l[i]*fac + rs;
            #pragma unroll
            for (int j = 0; j < 8; j++) o[i][j] *= fac;
        }

        // stage P^T
        #pragma unroll
        for (int i = 0; i < 4; i++)
            #pragma unroll
            for (int j = 0; j < 4; j++)
                sPT[(tx*4 + j)*68 + ty*4 + i] = acc[i][j];
        __syncthreads();

        // O += P @ V
        #pragma unroll 2
        for (int tt = 0; tt < 64; tt++) {
            float4 pf = *(const float4*)&sPT[tt*68 + ty*4];
            float4 va = *(const float4*)&sV[tt*128 + tx*4];
            float4 vb = *(const float4*)&sV[tt*128 + 64 + tx*4];
            float pr[4] = {pf.x, pf.y, pf.z, pf.w};
            #pragma unroll
            for (int i = 0; i < 4; i++) {
                o[i][0] += pr[i]*va.x; o[i][1] += pr[i]*va.y;
                o[i][2] += pr[i]*va.z; o[i][3] += pr[i]*va.w;
                o[i][4] += pr[i]*vb.x; o[i][5] += pr[i]*vb.y;
                o[i][6] += pr[i]*vb.z; o[i][7] += pr[i]*vb.w;
            }
        }
    }

    // ---- epilogue: normalize, gate-combine with pv, fuse out_w GEMM ----
    float gv  = 1.f / (1.f + __expf(-gate[h]));
    float omg = 1.f - gv;
    float pvv[8];
    #pragma unroll
    for (int j = 0; j < 4; j++) {
        pvv[j]   = g_pv[bh*128 + tx*4 + j];
        pvv[4+j] = g_pv[bh*128 + 64 + tx*4 + j];
    }

    float* oT = sm;   // [128 d][68 r], overwrites qT (done with it)
    #pragma unroll
    for (int i = 0; i < 4; i++) {
        float inv = 1.f / l[i];
        #pragma unroll
        for (int j = 0; j < 8; j++) {
            int d = (j < 4) ? (tx*4 + j) : (64 + tx*4 + (j - 4));
            oT[d*68 + ty*4 + i] = omg * o[i][j] * inv + gv * pvv[j];
        }
    }
    __syncthreads();   // GEMM2 readers of sPT done; oT visible

    float* owT = sm + 25600;   // [64 c'][68 c]
    for (int i = tid; i < 4096; i += 256) {
        int cp = i & 63, c = i >> 6;
        owT[cp*68 + c] = out_w[c*64 + cp];
    }
    __syncthreads();

    float fac2[2][4][4] = {};
    #pragma unroll 2
    for (int cp = 0; cp < 64; cp++) {
        float4 o0 = *(const float4*)&oT[cp*68 + ty*4];
        float4 o1 = *(const float4*)&oT[(64 + cp)*68 + ty*4];
        float4 wf = *(const float4*)&owT[cp*68 + tx*4];
        float wr[4] = {wf.x, wf.y, wf.z, wf.w};
        float a0[4] = {o0.x, o0.y, o0.z, o0.w};
        float a1[4] = {o1.x, o1.y, o1.z, o1.w};
        #pragma unroll
        for (int i = 0; i < 4; i++)
            #pragma unroll
            for (int j = 0; j < 4; j++) {
                fac2[0][i][j] += a0[i] * wr[j];
                fac2[1][i][j] += a1[i] * wr[j];
            }
    }

    float ob[4];
    #pragma unroll
    for (int j = 0; j < 4; j++) ob[j] = out_b[tx*4 + j];

    #pragma unroll
    for (int ws = 0; ws < 2; ws++) {
        int w = h*2 + ws;
        #pragma unroll
        for (int i = 0; i < 4; i++) {
            int s = s0 + ty*4 + i;
            float4 r;
            r.x = fac2[ws][i][0] + ob[0];
            r.y = fac2[ws][i][1] + ob[1];
            r.z = fac2[ws][i][2] + ob[2];
            r.w = fac2[ws][i][3] + ob[3];
            *(float4*)&out[(((size_t)b*1024 + s)*8 + w)*64 + tx*4] = r;
        }
    }
}

// ---------------- launch ----------------
extern "C" void kernel_launch(void* const* d_in, const int* in_sizes, int n_in,
                              void* d_out, int out_size) {
    const float* x        = (const float*)d_in[0];
    const float* pos      = (const float*)d_in[1];
    const float* strength = (const float*)d_in[2];
    const int*   embid    = (const int*)  d_in[3];
    const float* qw       = (const float*)d_in[4];
    const float* kw       = (const float*)d_in[5];
    const float* vw       = (const float*)d_in[6];
    const float* pw1      = (const float*)d_in[7];
    const float* pb1      = (const float*)d_in[8];
    const float* pw2      = (const float*)d_in[9];
    const float* pb2      = (const float*)d_in[10];
    const float* hw       = (const float*)d_in[11];
    // d_in[12] = head_b (cancels in softmax)
    const float* gate     = (const float*)d_in[13];
    const float* ow       = (const float*)d_in[14];
    const float* ob       = (const float*)d_in[15];
    const float* sw       = (const float*)d_in[16];
    const float* sb       = (const float*)d_in[17];
    float* out = (float*)d_out;

    cudaFuncSetAttribute(k_proj, cudaFuncAttributeMaxDynamicSharedMemorySize, 69632);
    cudaFuncSetAttribute(k_attn, cudaFuncAttributeMaxDynamicSharedMemorySize, 119808);

    k_svec<<<1, 64>>>(strength, sw, sb);
    k_proj<<<dim3(128, 4), 256, 69632>>>(x, qw, kw, vw, embid);
    k_pos<<<16, 256>>>(pos, pw1, pb1, pw2, pb2, hw);
    k_pv<<<16, 128>>>();
    k_attn<<<dim3(16, 16), 256, 119808>>>(gate, ow, ob, out);
}

// round 2
// speedup vs baseline: 1.1171x; 1.1171x over previous
#include <cuda_runtime.h>

typedef unsigned long long ULL;

// ---------------- f32x2 packed-FMA helpers ----------------
__device__ __forceinline__ void fma2(ULL &d, ULL a, ULL b) {
    asm("fma.rn.f32x2 %0, %1, %2, %0;" : "+l"(d) : "l"(a), "l"(b));
}
__device__ __forceinline__ void mul2(ULL &d, ULL b) {
    asm("mul.rn.f32x2 %0, %0, %1;" : "+l"(d) : "l"(b));
}
__device__ __forceinline__ ULL dup2(float f) {
    ULL r; asm("mov.b64 %0, {%1, %1};" : "=l"(r) : "f"(f)); return r;
}
__device__ __forceinline__ float2 unpk(ULL v) {
    float2 r; asm("mov.b64 {%0, %1}, %2;" : "=f"(r.x), "=f"(r.y) : "l"(v)); return r;
}

// ---------------- problem constants ----------------
#define BB   4
#define SS   1024
#define HH   4
#define HD   128

// ---------------- device scratch ----------------
__device__ float g_svec[64];
__device__ float g_q[BB*HH*SS*HD];
__device__ float g_k[BB*HH*SS*HD];
__device__ float g_v[BB*HH*SS*HD];
__device__ float g_nega[BB*HH*SS];     // -(ph @ head_w^T) per (b,h,t)
__device__ float g_pstat[32];          // per-bh {max, 1/sum}
__device__ float g_pvpart[16*8*128];   // partial pv
__device__ float g_pv[BB*HH*HD];       // pos_attn @ v (row-constant)

// ---------------- K0: strength projection ----------------
__global__ void k_svec(const float* __restrict__ strength,
                       const float* __restrict__ str_w,
                       const float* __restrict__ str_b) {
    int d = threadIdx.x;            // 64 threads
    float s = 0.f;
    #pragma unroll 8
    for (int i = 0; i < 512; i++) s += str_w[d*512 + i] * strength[i];
    g_svec[d] = s + str_b[d];
}

// ---------------- K1: q/k/v projections (f32x2) ----------------
// y[b,s,w,d] = sum_c x[b,c,s,w] * E[d,c] + svec[d]
// stored as [b][h][s][j] with h=w>>1, j=((w&1)<<6)|d
__global__ __launch_bounds__(256) void k_proj(
    const float* __restrict__ x,
    const float* __restrict__ qw, const float* __restrict__ kw,
    const float* __restrict__ vw, const int* __restrict__ embid)
{
    extern __shared__ float sm[];
    float* xd = sm;            // [64 c][132] duplicated x: xd[c][2m]=xd[c][2m+1]=x
    float* qT = sm + 8448;     // [64 c][68] cols d
    float* kT = sm + 12800;
    float* vT = sm + 17152;

    const int sblk = blockIdx.x;        // 128 s-blocks of 8
    const int b    = blockIdx.y;
    const int s0   = sblk * 8;
    const int tid  = threadIdx.x;
    const int id   = embid[0];
    const float* qwb = qw + (size_t)id * 4096;
    const float* kwb = kw + (size_t)id * 4096;
    const float* vwb = vw + (size_t)id * 4096;

    for (int i = tid; i < 4096; i += 256) {
        int c = i >> 6, mm = i & 63;
        int sl = mm >> 3, w = mm & 7;
        float xv = x[(((size_t)b*64 + c)*1024 + (s0 + sl))*8 + w];
        xd[c*132 + 2*mm]     = xv;
        xd[c*132 + 2*mm + 1] = xv;
        int d2 = i >> 6, c2 = i & 63;
        qT[c2*68 + d2] = qwb[d2*64 + c2];
        kT[c2*68 + d2] = kwb[d2*64 + c2];
        vT[c2*68 + d2] = vwb[d2*64 + c2];
    }
    __syncthreads();

    const int tx = tid & 15, ty = tid >> 4;
    ULL aq[4][2] = {}, ak[4][2] = {}, av[4][2] = {};
    #pragma unroll 2
    for (int c = 0; c < 64; c++) {
        ulonglong2 qp = *(const ulonglong2*)(qT + c*68 + tx*4);
        ulonglong2 kp = *(const ulonglong2*)(kT + c*68 + tx*4);
        ulonglong2 vp = *(const ulonglong2*)(vT + c*68 + tx*4);
        ulonglong2 xa = *(const ulonglong2*)(xd + c*132 + ty*8);
        ulonglong2 xb = *(const ulonglong2*)(xd + c*132 + ty*8 + 4);
        fma2(aq[0][0], xa.x, qp.x); fma2(aq[0][1], xa.x, qp.y);
        fma2(aq[1][0], xa.y, qp.x); fma2(aq[1][1], xa.y, qp.y);
        fma2(aq[2][0], xb.x, qp.x); fma2(aq[2][1], xb.x, qp.y);
        fma2(aq[3][0], xb.y, qp.x); fma2(aq[3][1], xb.y, qp.y);
        fma2(ak[0][0], xa.x, kp.x); fma2(ak[0][1], xa.x, kp.y);
        fma2(ak[1][0], xa.y, kp.x); fma2(ak[1][1], xa.y, kp.y);
        fma2(ak[2][0], xb.x, kp.x); fma2(ak[2][1], xb.x, kp.y);
        fma2(ak[3][0], xb.y, kp.x); fma2(ak[3][1], xb.y, kp.y);
        fma2(av[0][0], xa.x, vp.x); fma2(av[0][1], xa.x, vp.y);
        fma2(av[1][0], xa.y, vp.x); fma2(av[1][1], xa.y, vp.y);
        fma2(av[2][0], xb.x, vp.x); fma2(av[2][1], xb.x, vp.y);
        fma2(av[3][0], xb.y, vp.x); fma2(av[3][1], xb.y, vp.y);
    }

    float sv[4];
    #pragma unroll
    for (int j = 0; j < 4; j++) sv[j] = g_svec[tx*4 + j];

    #pragma unroll
    for (int i = 0; i < 4; i++) {
        int mm = ty*4 + i;
        int sl = mm >> 3, w = mm & 7;
        int h = w >> 1;
        int jb = ((w & 1) << 6) + tx*4;
        size_t base = (((size_t)(b*4 + h)*1024 + (s0 + sl))*128 + jb);
        float2 a0, a1; float4 o;
        a0 = unpk(aq[i][0]); a1 = unpk(aq[i][1]);
        o.x = a0.x+sv[0]; o.y = a0.y+sv[1]; o.z = a1.x+sv[2]; o.w = a1.y+sv[3];
        *(float4*)&g_q[base] = o;
        a0 = unpk(ak[i][0]); a1 = unpk(ak[i][1]);
        o.x = a0.x+sv[0]; o.y = a0.y+sv[1]; o.z = a1.x+sv[2]; o.w = a1.y+sv[3];
        *(float4*)&g_k[base] = o;
        a0 = unpk(av[i][0]); a1 = unpk(av[i][1]);
        o.x = a0.x+sv[0]; o.y = a0.y+sv[1]; o.z = a1.x+sv[2]; o.w = a1.y+sv[3];
        *(float4*)&g_v[base] = o;
    }
}

// ---------------- K2a: positional MLP (collapsed) ----------------
__global__ void k_pos(const float* __restrict__ pos,
                      const float* __restrict__ w1, const float* __restrict__ b1,
                      const float* __restrict__ w2, const float* __restrict__ b2,
                      const float* __restrict__ hw)
{
    int idx = blockIdx.x * blockDim.x + threadIdx.x;   // b*1024 + s
    if (idx >= BB*SS) return;
    float p0 = pos[idx*3+0], p1 = pos[idx*3+1], p2 = pos[idx*3+2];
    float h1[3];
    #pragma unroll
    for (int j = 0; j < 3; j++)
        h1[j] = fmaxf(0.f, w1[j*3+0]*p0 + w1[j*3+1]*p1 + w1[j*3+2]*p2 + b1[j]);
    float ph[8];
    #pragma unroll
    for (int d = 0; d < 8; d++)
        ph[d] = w2[d*3+0]*h1[0] + w2[d*3+1]*h1[1] + w2[d*3+2]*h1[2] + b2[d];
    int b = idx >> 10, s = idx & 1023;
    #pragma unroll
    for (int h = 0; h < 4; h++) {
        float a = 0.f;
        #pragma unroll
        for (int d = 0; d < 8; d++) a += ph[d] * hw[h*8 + d];
        g_nega[((size_t)(b*4 + h))*1024 + s] = -a;   // head_b cancels in softmax
    }
}

// ---------------- K2b: softmax stats per bh ----------------
__global__ void k_psm() {
    __shared__ float red[256];
    int bh = blockIdx.x, tid = threadIdx.x;
    const float* na = g_nega + (size_t)bh*1024;
    float mx = -1e30f;
    for (int t = tid; t < 1024; t += 256) mx = fmaxf(mx, na[t]);
    red[tid] = mx; __syncthreads();
    for (int s = 128; s > 0; s >>= 1) { if (tid < s) red[tid] = fmaxf(red[tid], red[tid+s]); __syncthreads(); }
    mx = red[0]; __syncthreads();
    float sum = 0.f;
    for (int t = tid; t < 1024; t += 256) sum += __expf(na[t] - mx);
    red[tid] = sum; __syncthreads();
    for (int s = 128; s > 0; s >>= 1) { if (tid < s) red[tid] += red[tid+s]; __syncthreads(); }
    if (tid == 0) { g_pstat[bh*2] = mx; g_pstat[bh*2+1] = 1.f / red[0]; }
}

// ---------------- K2c: partial pv per (bh, 128-t chunk) ----------------
__global__ __launch_bounds__(256) void k_pvp() {
    __shared__ float sw[128];
    __shared__ float red[256];
    int g = blockIdx.x, bh = blockIdx.y, tid = threadIdx.x;
    float mm = g_pstat[bh*2], invl = g_pstat[bh*2+1];
    if (tid < 128) sw[tid] = __expf(g_nega[(size_t)bh*1024 + g*128 + tid] - mm) * invl;
    __syncthreads();
    int d = tid & 127, half = tid >> 7;
    const float* vv = g_v + (size_t)bh*131072 + (size_t)g*128*128;
    float acc = 0.f;
    #pragma unroll 8
    for (int k = 0; k < 64; k++) {
        int tt = half*64 + k;
        acc += sw[tt] * vv[(size_t)tt*128 + d];
    }
    red[tid] = acc; __syncthreads();
    if (tid < 128) g_pvpart[((size_t)bh*8 + g)*128 + d] = red[tid] + red[tid + 128];
}

// ---------------- K2d: reduce partials ----------------
__global__ void k_pvred() {
    int bh = blockIdx.x, d = threadIdx.x;   // 128 threads
    float s = 0.f;
    #pragma unroll
    for (int gg = 0; gg < 8; gg++) s += g_pvpart[((size_t)bh*8 + gg)*128 + d];
    g_pv[bh*128 + d] = s;
}

// ---------------- K3: flash attention + gate combine + out_w GEMM (f32x2) ----------------
// grid (16 s-tiles, 16 bh), 256 threads (16x16), thread tile 4x4 (QK) / 4x8 (PV)
__global__ __launch_bounds__(256) void k_attn(
    const float* __restrict__ gate, const float* __restrict__ out_w,
    const float* __restrict__ out_b, float* __restrict__ out)
{
    extern __shared__ float sm[];
    float* qd  = sm;            // [128 kk][132]  duplicated scaled q: qd[kk][2r]=qd[kk][2r+1]
    float* kT  = sm + 16896;    // [128 kk][68]
    float* sV  = sm + 25600;    // [64 t][128 d]
    float* sPd = sm + 33792;    // [64 r][136]    duplicated P: sPd[r][2t]=sPd[r][2t+1]
    // epilogue reuse: oT = sm (128x68), owT = sm + 8704 (64x68) — inside qd region

    const int stile = blockIdx.x, bh = blockIdx.y;
    const int b = bh >> 2, h = bh & 3;
    const int s0 = stile * 64;
    const int tid = threadIdx.x, tx = tid & 15, ty = tid >> 4;

    const float* Q = g_q + (size_t)bh*131072;
    const float* K = g_k + (size_t)bh*131072;
    const float* V = g_v + (size_t)bh*131072;
    const float scale = 0.08838834764831845f;   // 1/sqrt(128)

    // Q tile: transposed + pre-scaled + duplicated
    for (int i = tid; i < 8192; i += 256) {
        int r = i >> 7, kk = i & 127;
        float v = Q[(size_t)(s0 + r)*128 + kk] * scale;
        qd[kk*132 + 2*r]     = v;
        qd[kk*132 + 2*r + 1] = v;
    }

    float m[4], l[4];
    ULL o2[4][4];
    #pragma unroll
    for (int i = 0; i < 4; i++) {
        m[i] = -1e30f; l[i] = 0.f;
        #pragma unroll
        for (int j = 0; j < 4; j++) o2[i][j] = 0ULL;
    }

    for (int t0 = 0; t0 < 1024; t0 += 64) {
        __syncthreads();
        for (int i = tid; i < 8192; i += 256) {
            int c = i >> 7, kk = i & 127;
            kT[kk*68 + c] = K[(size_t)(t0 + c)*128 + kk];
            sV[i] = V[(size_t)t0*128 + i];
        }
        __syncthreads();

        // S = Qs @ K^T (64x64): pairs along key-cols, dup'd q broadcast
        ULL acc2[4][2];
        #pragma unroll
        for (int i = 0; i < 4; i++) { acc2[i][0] = 0ULL; acc2[i][1] = 0ULL; }
        #pragma unroll 2
        for (int kk = 0; kk < 128; kk++) {
            ulonglong2 kp = *(const ulonglong2*)(kT + kk*68 + tx*4);
            ulonglong2 qa = *(const ulonglong2*)(qd + kk*132 + ty*8);
            ulonglong2 qb = *(const ulonglong2*)(qd + kk*132 + ty*8 + 4);
            fma2(acc2[0][0], qa.x, kp.x); fma2(acc2[0][1], qa.x, kp.y);
            fma2(acc2[1][0], qa.y, kp.x); fma2(acc2[1][1], qa.y, kp.y);
            fma2(acc2[2][0], qb.x, kp.x); fma2(acc2[2][1], qb.x, kp.y);
            fma2(acc2[3][0], qb.y, kp.x); fma2(acc2[3][1], qb.y, kp.y);
        }

        // online softmax (row reductions across tx = half-warp shuffles)
        #pragma unroll
        for (int i = 0; i < 4; i++) {
            float2 c0 = unpk(acc2[i][0]), c1 = unpk(acc2[i][1]);
            float p0 = c0.x, p1 = c0.y, p2 = c1.x, p3 = c1.y;
            float tm = fmaxf(fmaxf(p0, p1), fmaxf(p2, p3));
            #pragma unroll
            for (int ofs = 1; ofs < 16; ofs <<= 1)
                tm = fmaxf(tm, __shfl_xor_sync(0xffffffffu, tm, ofs));
            float mn  = fmaxf(m[i], tm);
            float fac = __expf(m[i] - mn);
            m[i] = mn;
            p0 = __expf(p0 - mn); p1 = __expf(p1 - mn);
            p2 = __expf(p2 - mn); p3 = __expf(p3 - mn);
            float rs = p0 + p1 + p2 + p3;
            #pragma unroll
            for (int ofs = 1; ofs < 16; ofs <<= 1)
                rs += __shfl_xor_sync(0xffffffffu, rs, ofs);
            l[i] = l[i]*fac + rs;
            ULL fd = dup2(fac);
            mul2(o2[i][0], fd); mul2(o2[i][1], fd);
            mul2(o2[i][2], fd); mul2(o2[i][3], fd);
            // stage duplicated P: row r = ty*4+i, cols 2*(tx*4+j)
            int r = ty*4 + i;
            *(float4*)(sPd + r*136 + 8*tx)     = make_float4(p0, p0, p1, p1);
            *(float4*)(sPd + r*136 + 8*tx + 4) = make_float4(p2, p2, p3, p3);
        }
        __syncthreads();

        // O += P @ V : pairs along d-cols, dup'd p broadcast
        #pragma unroll 2
        for (int tt = 0; tt < 64; tt++) {
            ulonglong2 v0 = *(const ulonglong2*)(sV + tt*128 + tx*4);
            ulonglong2 v1 = *(const ulonglong2*)(sV + tt*128 + 64 + tx*4);
            const float* pr = sPd + 2*tt;
            ULL pd0 = *(const ULL*)(pr + (ty*4+0)*136);
            ULL pd1 = *(const ULL*)(pr + (ty*4+1)*136);
            ULL pd2 = *(const ULL*)(pr + (ty*4+2)*136);
            ULL pd3 = *(const ULL*)(pr + (ty*4+3)*136);
            fma2(o2[0][0], pd0, v0.x); fma2(o2[0][1], pd0, v0.y);
            fma2(o2[0][2], pd0, v1.x); fma2(o2[0][3], pd0, v1.y);
            fma2(o2[1][0], pd1, v0.x); fma2(o2[1][1], pd1, v0.y);
            fma2(o2[1][2], pd1, v1.x); fma2(o2[1][3], pd1, v1.y);
            fma2(o2[2][0], pd2, v0.x); fma2(o2[2][1], pd2, v0.y);
            fma2(o2[2][2], pd2, v1.x); fma2(o2[2][3], pd2, v1.y);
            fma2(o2[3][0], pd3, v0.x); fma2(o2[3][1], pd3, v0.y);
            fma2(o2[3][2], pd3, v1.x); fma2(o2[3][3], pd3, v1.y);
        }
    }

    // ---- epilogue: normalize, gate-combine with pv, fuse out_w GEMM ----
    float gv  = 1.f / (1.f + __expf(-gate[h]));
    float omg = 1.f - gv;
    float pvv[8];
    #pragma unroll
    for (int j = 0; j < 4; j++) {
        pvv[j]   = g_pv[bh*128 + tx*4 + j];
        pvv[4+j] = g_pv[bh*128 + 64 + tx*4 + j];
    }

    float* oT  = sm;           // [128 d][68 r] — overwrites qd (done with it)
    float* owT = sm + 8704;    // [64 c'][68 c]
    #pragma unroll
    for (int i = 0; i < 4; i++) {
        float inv = 1.f / l[i];
        float2 a = unpk(o2[i][0]), b2 = unpk(o2[i][1]);
        float2 c = unpk(o2[i][2]), e = unpk(o2[i][3]);
        float ov[8] = {a.x, a.y, b2.x, b2.y, c.x, c.y, e.x, e.y};
        #pragma unroll
        for (int j = 0; j < 8; j++) {
            int d = (j < 4) ? (tx*4 + j) : (64 + tx*4 + (j - 4));
            oT[d*68 + ty*4 + i] = omg * ov[j] * inv + gv * pvv[j];
        }
    }
    for (int i = tid; i < 4096; i += 256) {
        int cp = i & 63, cc = i >> 6;
        owT[cp*68 + cc] = out_w[cc*64 + cp];
    }
    __syncthreads();

    float fac2[2][4][4] = {};
    #pragma unroll 2
    for (int cp = 0; cp < 64; cp++) {
        float4 o0 = *(const float4*)&oT[cp*68 + ty*4];
        float4 o1 = *(const float4*)&oT[(64 + cp)*68 + ty*4];
        float4 wf = *(const float4*)&owT[cp*68 + tx*4];
        float wr[4] = {wf.x, wf.y, wf.z, wf.w};
        float a0[4] = {o0.x, o0.y, o0.z, o0.w};
        float a1[4] = {o1.x, o1.y, o1.z, o1.w};
        #pragma unroll
        for (int i = 0; i < 4; i++)
            #pragma unroll
            for (int j = 0; j < 4; j++) {
                fac2[0][i][j] += a0[i] * wr[j];
                fac2[1][i][j] += a1[i] * wr[j];
            }
    }

    float ob[4];
    #pragma unroll
    for (int j = 0; j < 4; j++) ob[j] = out_b[tx*4 + j];

    #pragma unroll
    for (int ws = 0; ws < 2; ws++) {
        int w = h*2 + ws;
        #pragma unroll
        for (int i = 0; i < 4; i++) {
            int s = s0 + ty*4 + i;
            float4 r;
            r.x = fac2[ws][i][0] + ob[0];
            r.y = fac2[ws][i][1] + ob[1];
            r.z = fac2[ws][i][2] + ob[2];
            r.w = fac2[ws][i][3] + ob[3];
            *(float4*)&out[(((size_t)b*1024 + s)*8 + w)*64 + tx*4] = r;
        }
    }
}

// ---------------- launch ----------------
extern "C" void kernel_launch(void* const* d_in, const int* in_sizes, int n_in,
                              void* d_out, int out_size) {
    const float* x        = (const float*)d_in[0];
    const float* pos      = (const float*)d_in[1];
    const float* strength = (const float*)d_in[2];
    const int*   embid    = (const int*)  d_in[3];
    const float* qw       = (const float*)d_in[4];
    const float* kw       = (const float*)d_in[5];
    const float* vw       = (const float*)d_in[6];
    const float* pw1      = (const float*)d_in[7];
    const float* pb1      = (const float*)d_in[8];
    const float* pw2      = (const float*)d_in[9];
    const float* pb2      = (const float*)d_in[10];
    const float* hw       = (const float*)d_in[11];
    // d_in[12] = head_b (cancels in softmax)
    const float* gate     = (const float*)d_in[13];
    const float* ow       = (const float*)d_in[14];
    const float* ob       = (const float*)d_in[15];
    const float* sw       = (const float*)d_in[16];
    const float* sb       = (const float*)d_in[17];
    float* out = (float*)d_out;

    cudaFuncSetAttribute(k_proj, cudaFuncAttributeMaxDynamicSharedMemorySize, 86016);
    cudaFuncSetAttribute(k_attn, cudaFuncAttributeMaxDynamicSharedMemorySize, 169984);

    k_svec<<<1, 64>>>(strength, sw, sb);
    k_proj<<<dim3(128, 4), 256, 86016>>>(x, qw, kw, vw, embid);
    k_pos<<<16, 256>>>(pos, pw1, pb1, pw2, pb2, hw);
    k_psm<<<16, 256>>>();
    k_pvp<<<dim3(8, 16), 256>>>();
    k_pvred<<<16, 128>>>();
    k_attn<<<dim3(16, 16), 256, 169984>>>(gate, ow, ob, out);
}

// round 3
// speedup vs baseline: 1.4695x; 1.3154x over previous
#include <cuda_runtime.h>

typedef unsigned long long ULL;

// ---------------- f32x2 packed-FMA helpers ----------------
__device__ __forceinline__ void fma2(ULL &d, ULL a, ULL b) {
    asm("fma.rn.f32x2 %0, %1, %2, %0;" : "+l"(d) : "l"(a), "l"(b));
}
__device__ __forceinline__ void mul2(ULL &d, ULL b) {
    asm("mul.rn.f32x2 %0, %0, %1;" : "+l"(d) : "l"(b));
}
__device__ __forceinline__ ULL dup2(float f) {
    ULL r; asm("mov.b64 %0, {%1, %1};" : "=l"(r) : "f"(f)); return r;
}
__device__ __forceinline__ float2 unpk(ULL v) {
    float2 r; asm("mov.b64 {%0, %1}, %2;" : "=f"(r.x), "=f"(r.y) : "l"(v)); return r;
}

// ---------------- problem constants ----------------
#define BB   4
#define SS   1024
#define HH   4
#define HD   128
#define PIT  132     // smem pitch for 128-wide transposed tiles (132 % 32 == 4)

// ---------------- device scratch ----------------
__device__ float g_svec[64];
__device__ float g_q[BB*HH*SS*HD];
__device__ float g_k[BB*HH*SS*HD];
__device__ float g_v[BB*HH*SS*HD];
__device__ float g_pv[BB*HH*HD];       // pos_attn @ v (row-constant)

// ---------------- K0: strength projection ----------------
__global__ void k_svec(const float* __restrict__ strength,
                       const float* __restrict__ str_w,
                       const float* __restrict__ str_b) {
    int d = threadIdx.x;            // 64 threads
    float s = 0.f;
    #pragma unroll 8
    for (int i = 0; i < 512; i++) s += str_w[d*512 + i] * strength[i];
    g_svec[d] = s + str_b[d];
}

// ---------------- K1: q/k/v projections (f32x2) ----------------
__global__ __launch_bounds__(256) void k_proj(
    const float* __restrict__ x,
    const float* __restrict__ qw, const float* __restrict__ kw,
    const float* __restrict__ vw, const int* __restrict__ embid)
{
    extern __shared__ float sm[];
    float* xd = sm;            // [64 c][132] duplicated x
    float* qT = sm + 8448;     // [64 c][68]
    float* kT = sm + 12800;
    float* vT = sm + 17152;

    const int sblk = blockIdx.x;
    const int b    = blockIdx.y;
    const int s0   = sblk * 8;
    const int tid  = threadIdx.x;
    const int id   = embid[0];
    const float* qwb = qw + (size_t)id * 4096;
    const float* kwb = kw + (size_t)id * 4096;
    const float* vwb = vw + (size_t)id * 4096;

    for (int i = tid; i < 4096; i += 256) {
        int c = i >> 6, mm = i & 63;
        int sl = mm >> 3, w = mm & 7;
        float xv = x[(((size_t)b*64 + c)*1024 + (s0 + sl))*8 + w];
        xd[c*132 + 2*mm]     = xv;
        xd[c*132 + 2*mm + 1] = xv;
        int d2 = i >> 6, c2 = i & 63;
        qT[c2*68 + d2] = qwb[d2*64 + c2];
        kT[c2*68 + d2] = kwb[d2*64 + c2];
        vT[c2*68 + d2] = vwb[d2*64 + c2];
    }
    __syncthreads();

    const int tx = tid & 15, ty = tid >> 4;
    ULL aq[4][2] = {}, ak[4][2] = {}, av[4][2] = {};
    #pragma unroll 2
    for (int c = 0; c < 64; c++) {
        ulonglong2 qp = *(const ulonglong2*)(qT + c*68 + tx*4);
        ulonglong2 kp = *(const ulonglong2*)(kT + c*68 + tx*4);
        ulonglong2 vp = *(const ulonglong2*)(vT + c*68 + tx*4);
        ulonglong2 xa = *(const ulonglong2*)(xd + c*132 + ty*8);
        ulonglong2 xb = *(const ulonglong2*)(xd + c*132 + ty*8 + 4);
        fma2(aq[0][0], xa.x, qp.x); fma2(aq[0][1], xa.x, qp.y);
        fma2(aq[1][0], xa.y, qp.x); fma2(aq[1][1], xa.y, qp.y);
        fma2(aq[2][0], xb.x, qp.x); fma2(aq[2][1], xb.x, qp.y);
        fma2(aq[3][0], xb.y, qp.x); fma2(aq[3][1], xb.y, qp.y);
        fma2(ak[0][0], xa.x, kp.x); fma2(ak[0][1], xa.x, kp.y);
        fma2(ak[1][0], xa.y, kp.x); fma2(ak[1][1], xa.y, kp.y);
        fma2(ak[2][0], xb.x, kp.x); fma2(ak[2][1], xb.x, kp.y);
        fma2(ak[3][0], xb.y, kp.x); fma2(ak[3][1], xb.y, kp.y);
        fma2(av[0][0], xa.x, vp.x); fma2(av[0][1], xa.x, vp.y);
        fma2(av[1][0], xa.y, vp.x); fma2(av[1][1], xa.y, vp.y);
        fma2(av[2][0], xb.x, vp.x); fma2(av[2][1], xb.x, vp.y);
        fma2(av[3][0], xb.y, vp.x); fma2(av[3][1], xb.y, vp.y);
    }

    float sv[4];
    #pragma unroll
    for (int j = 0; j < 4; j++) sv[j] = g_svec[tx*4 + j];

    #pragma unroll
    for (int i = 0; i < 4; i++) {
        int mm = ty*4 + i;
        int sl = mm >> 3, w = mm & 7;
        int h = w >> 1;
        int jb = ((w & 1) << 6) + tx*4;
        size_t base = (((size_t)(b*4 + h)*1024 + (s0 + sl))*128 + jb);
        float2 a0, a1; float4 o;
        a0 = unpk(aq[i][0]); a1 = unpk(aq[i][1]);
        o.x = a0.x+sv[0]; o.y = a0.y+sv[1]; o.z = a1.x+sv[2]; o.w = a1.y+sv[3];
        *(float4*)&g_q[base] = o;
        a0 = unpk(ak[i][0]); a1 = unpk(ak[i][1]);
        o.x = a0.x+sv[0]; o.y = a0.y+sv[1]; o.z = a1.x+sv[2]; o.w = a1.y+sv[3];
        *(float4*)&g_k[base] = o;
        a0 = unpk(av[i][0]); a1 = unpk(av[i][1]);
        o.x = a0.x+sv[0]; o.y = a0.y+sv[1]; o.z = a1.x+sv[2]; o.w = a1.y+sv[3];
        *(float4*)&g_v[base] = o;
    }
}

// ---------------- K2: fused positional branch -> g_pv ----------------
// grid 16 (bh), 512 threads
__global__ __launch_bounds__(512) void k_posb(
    const float* __restrict__ pos,
    const float* __restrict__ w1, const float* __restrict__ b1,
    const float* __restrict__ w2, const float* __restrict__ b2,
    const float* __restrict__ hw)
{
    __shared__ float sn[1024];
    __shared__ float red[512];
    const int bh = blockIdx.x, b = bh >> 2, h = bh & 3;
    const int tid = threadIdx.x;

    float hwv[8];
    #pragma unroll
    for (int d = 0; d < 8; d++) hwv[d] = hw[h*8 + d];

    for (int s = tid; s < 1024; s += 512) {
        int idx = b*1024 + s;
        float p0 = pos[idx*3+0], p1 = pos[idx*3+1], p2 = pos[idx*3+2];
        float h1[3];
        #pragma unroll
        for (int j = 0; j < 3; j++)
            h1[j] = fmaxf(0.f, w1[j*3+0]*p0 + w1[j*3+1]*p1 + w1[j*3+2]*p2 + b1[j]);
        float a = 0.f;
        #pragma unroll
        for (int d = 0; d < 8; d++) {
            float ph = w2[d*3+0]*h1[0] + w2[d*3+1]*h1[1] + w2[d*3+2]*h1[2] + b2[d];
            a += ph * hwv[d];
        }
        sn[s] = -a;      // head_b cancels in softmax
    }
    __syncthreads();

    float mx = fmaxf(sn[tid], sn[tid + 512]);
    red[tid] = mx; __syncthreads();
    for (int s = 256; s > 0; s >>= 1) { if (tid < s) red[tid] = fmaxf(red[tid], red[tid+s]); __syncthreads(); }
    mx = red[0]; __syncthreads();

    float e0 = __expf(sn[tid] - mx), e1 = __expf(sn[tid+512] - mx);
    red[tid] = e0 + e1; __syncthreads();
    for (int s = 256; s > 0; s >>= 1) { if (tid < s) red[tid] += red[tid+s]; __syncthreads(); }
    float inv = 1.f / red[0];
    __syncthreads();
    sn[tid] = e0 * inv; sn[tid+512] = e1 * inv;
    __syncthreads();

    const int d = tid & 127, grp = tid >> 7;   // 4 groups of 256 t
    const float* vv = g_v + (size_t)bh*131072;
    float acc = 0.f;
    #pragma unroll 4
    for (int k = 0; k < 256; k++) {
        int t = grp*256 + k;
        acc += sn[t] * vv[(size_t)t*128 + d];
    }
    red[tid] = acc; __syncthreads();
    if (tid < 128)
        g_pv[bh*128 + d] = red[tid] + red[tid+128] + red[tid+256] + red[tid+384];
}

// ---------------- K3: flash attention, 128x128 tiles, 8x8/thread (f32x2) ----------------
// grid (8 stiles, 16 bh), 256 threads (tx 0..15 = keys/dcols, ty 0..15 = queries)
__global__ __launch_bounds__(256) void k_attn(
    const float* __restrict__ gate, const float* __restrict__ out_w,
    const float* __restrict__ out_b, float* __restrict__ out)
{
    extern __shared__ float sm[];
    float* qT  = sm;                 // [128 kk][PIT] q^T, pre-scaled
    float* kT  = sm + 128*PIT;       // [128 kk][PIT] k^T; reused as sPT [t][PIT] (swizzled)
    float* sV  = sm + 2*128*PIT;     // [128 t][128 d]
    // epilogue: oT = sm (128 d x PIT r, swizzled), owT = sm + 128*PIT (64x68)

    const int stile = blockIdx.x, bh = blockIdx.y;
    const int b = bh >> 2, h = bh & 3;
    const int s0 = stile * 128;
    const int tid = threadIdx.x, tx = tid & 15, ty = tid >> 4;

    const float* Q = g_q + (size_t)bh*131072;
    const float* K = g_k + (size_t)bh*131072;
    const float* V = g_v + (size_t)bh*131072;
    const float scale = 0.08838834764831845f;   // 1/sqrt(128)

    // stage Q^T (coalesced LDG over kk, 4-way-conflict STS: pitch%32==4, lane=kk)
    for (int i = tid; i < 16384; i += 256) {
        int kk = i & 127, r = i >> 7;
        qT[kk*PIT + r] = Q[(size_t)(s0 + r)*128 + kk] * scale;
    }

    float m[8], l[8];
    ULL o2[8][4];
    #pragma unroll
    for (int i = 0; i < 8; i++) {
        m[i] = -1e30f; l[i] = 0.f;
        #pragma unroll
        for (int j = 0; j < 4; j++) o2[i][j] = 0ULL;
    }

    for (int t0 = 0; t0 < 1024; t0 += 128) {
        __syncthreads();   // prev PV reads of sPT/sV done
        for (int i = tid; i < 16384; i += 256) {
            int kk = i & 127, c = i >> 7;
            kT[kk*PIT + c] = K[(size_t)(t0 + c)*128 + kk];
        }
        for (int i = tid; i < 4096; i += 256) {
            int t = i >> 5, d4 = i & 31;
            *(float4*)&sV[t*128 + d4*4] = *(const float4*)&V[(size_t)(t0 + t)*128 + d4*4];
        }
        __syncthreads();

        // ---- S = Qs @ K^T (128x128), 8x8 per thread ----
        ULL acc2[8][4];
        #pragma unroll
        for (int i = 0; i < 8; i++)
            #pragma unroll
            for (int j = 0; j < 4; j++) acc2[i][j] = 0ULL;

        #pragma unroll 2
        for (int kk = 0; kk < 128; kk++) {
            ulonglong2 kp0 = *(const ulonglong2*)(kT + kk*PIT + tx*8);      // 4 key pairs
            float4 qa = *(const float4*)(qT + kk*PIT + ty*8);
            float4 qb = *(const float4*)(qT + kk*PIT + ty*8 + 4);
            ULL qd[8];
            qd[0] = dup2(qa.x); qd[1] = dup2(qa.y); qd[2] = dup2(qa.z); qd[3] = dup2(qa.w);
            qd[4] = dup2(qb.x); qd[5] = dup2(qb.y); qd[6] = dup2(qb.z); qd[7] = dup2(qb.w);
            ulonglong2 kp1 = *(const ulonglong2*)(kT + kk*PIT + tx*8 + 4);
            #pragma unroll
            for (int i = 0; i < 8; i++) {
                fma2(acc2[i][0], qd[i], kp0.x);
                fma2(acc2[i][1], qd[i], kp0.y);
                fma2(acc2[i][2], qd[i], kp1.x);
                fma2(acc2[i][3], qd[i], kp1.y);
            }
        }
        __syncthreads();   // all kT reads done before P overwrites it

        // ---- online softmax + stage P^T into kT region (swizzled) ----
        float* sPT = kT;
        const int swzst = tx << 2;               // ((t>>3)&15)<<2, t=tx*8+jj
        #pragma unroll
        for (int i = 0; i < 8; i++) {
            float2 u0 = unpk(acc2[i][0]), u1 = unpk(acc2[i][1]);
            float2 u2 = unpk(acc2[i][2]), u3 = unpk(acc2[i][3]);
            float p[8] = {u0.x,u0.y,u1.x,u1.y,u2.x,u2.y,u3.x,u3.y};
            float tm = p[0];
            #pragma unroll
            for (int j = 1; j < 8; j++) tm = fmaxf(tm, p[j]);
            #pragma unroll
            for (int ofs = 1; ofs < 16; ofs <<= 1)
                tm = fmaxf(tm, __shfl_xor_sync(0xffffffffu, tm, ofs));
            float mn  = fmaxf(m[i], tm);
            float fac = __expf(m[i] - mn);
            m[i] = mn;
            float rs = 0.f;
            #pragma unroll
            for (int j = 0; j < 8; j++) { p[j] = __expf(p[j] - mn); rs += p[j]; }
            #pragma unroll
            for (int ofs = 1; ofs < 16; ofs <<= 1)
                rs += __shfl_xor_sync(0xffffffffu, rs, ofs);
            l[i] = l[i]*fac + rs;
            ULL fd = dup2(fac);
            #pragma unroll
            for (int j = 0; j < 4; j++) mul2(o2[i][j], fd);
            int col = (ty*8 + i) ^ swzst;
            #pragma unroll
            for (int j = 0; j < 8; j++)
                sPT[(tx*8 + j)*PIT + col] = p[j];
        }
        __syncthreads();

        // ---- O += P @ V ----
        #pragma unroll 2
        for (int tt = 0; tt < 128; tt++) {
            int swz = ((tt >> 3) & 15) << 2;
            float4 pa = *(const float4*)(sPT + tt*PIT + ((ty*8) ^ swz));
            float4 pb = *(const float4*)(sPT + tt*PIT + ((ty*8 + 4) ^ swz));
            ulonglong2 v0 = *(const ulonglong2*)(sV + tt*128 + tx*8);
            ulonglong2 v1 = *(const ulonglong2*)(sV + tt*128 + tx*8 + 4);
            ULL pd[8];
            pd[0] = dup2(pa.x); pd[1] = dup2(pa.y); pd[2] = dup2(pa.z); pd[3] = dup2(pa.w);
            pd[4] = dup2(pb.x); pd[5] = dup2(pb.y); pd[6] = dup2(pb.z); pd[7] = dup2(pb.w);
            #pragma unroll
            for (int i = 0; i < 8; i++) {
                fma2(o2[i][0], pd[i], v0.x);
                fma2(o2[i][1], pd[i], v0.y);
                fma2(o2[i][2], pd[i], v1.x);
                fma2(o2[i][3], pd[i], v1.y);
            }
        }
    }

    // ---- epilogue: normalize + gate-combine, fused out_w GEMM ----
    float gv  = 1.f / (1.f + __expf(-gate[h]));
    float omg = 1.f - gv;
    float pvv[8];
    #pragma unroll
    for (int j = 0; j < 8; j++) pvv[j] = g_pv[bh*128 + tx*8 + j];

    __syncthreads();   // PV reads done; reuse smem
    float* oT  = sm;              // [128 d][PIT r], swizzled cols: r ^ ((d>>3&15)<<2)
    float* owT = sm + 128*PIT;    // [64 cp][68 c]

    const int swzo = tx << 2;     // (d>>3)&15 = tx for d = tx*8+jj
    #pragma unroll
    for (int i = 0; i < 8; i++) {
        float invl = 1.f / l[i];
        float2 u0 = unpk(o2[i][0]), u1 = unpk(o2[i][1]);
        float2 u2 = unpk(o2[i][2]), u3 = unpk(o2[i][3]);
        float ov[8] = {u0.x,u0.y,u1.x,u1.y,u2.x,u2.y,u3.x,u3.y};
        int col = (ty*8 + i) ^ swzo;
        #pragma unroll
        for (int j = 0; j < 8; j++)
            oT[(tx*8 + j)*PIT + col] = omg * ov[j] * invl + gv * pvv[j];
    }
    for (int i = tid; i < 4096; i += 256) {
        int cp = i & 63, cc = i >> 6;
        owT[cp*68 + cc] = out_w[cc*64 + cp];
    }
    __syncthreads();

    // GEMM2: two 128x64x64 halves; row-pairs packed for f32x2
    ULL facp[2][4][4];
    #pragma unroll
    for (int ws = 0; ws < 2; ws++)
        #pragma unroll
        for (int rp = 0; rp < 4; rp++)
            #pragma unroll
            for (int j = 0; j < 4; j++) facp[ws][rp][j] = 0ULL;

    #pragma unroll 2
    for (int cp = 0; cp < 64; cp++) {
        int swz0 = ((cp >> 3) & 15) << 2;
        int swz1 = (((cp + 64) >> 3) & 15) << 2;
        const float* r0 = oT + cp*PIT;
        const float* r1 = oT + (cp + 64)*PIT;
        ulonglong2 oa = { *(const ULL*)(r0 + ((ty*8) ^ swz0)),
                          *(const ULL*)(r0 + ((ty*8 + 2) ^ swz0)) };
        ulonglong2 ob = { *(const ULL*)(r0 + ((ty*8 + 4) ^ swz0)),
                          *(const ULL*)(r0 + ((ty*8 + 6) ^ swz0)) };
        ulonglong2 oc = { *(const ULL*)(r1 + ((ty*8) ^ swz1)),
                          *(const ULL*)(r1 + ((ty*8 + 2) ^ swz1)) };
        ulonglong2 od = { *(const ULL*)(r1 + ((ty*8 + 4) ^ swz1)),
                          *(const ULL*)(r1 + ((ty*8 + 6) ^ swz1)) };
        float4 wf = *(const float4*)&owT[cp*68 + tx*4];
        ULL wd[4] = {dup2(wf.x), dup2(wf.y), dup2(wf.z), dup2(wf.w)};
        #pragma unroll
        for (int j = 0; j < 4; j++) {
            fma2(facp[0][0][j], oa.x, wd[j]);
            fma2(facp[0][1][j], oa.y, wd[j]);
            fma2(facp[0][2][j], ob.x, wd[j]);
            fma2(facp[0][3][j], ob.y, wd[j]);
            fma2(facp[1][0][j], oc.x, wd[j]);
            fma2(facp[1][1][j], oc.y, wd[j]);
            fma2(facp[1][2][j], od.x, wd[j]);
            fma2(facp[1][3][j], od.y, wd[j]);
        }
    }

    float ob4[4];
    #pragma unroll
    for (int j = 0; j < 4; j++) ob4[j] = out_b[tx*4 + j];

    #pragma unroll
    for (int ws = 0; ws < 2; ws++) {
        int w = h*2 + ws;
        #pragma unroll
        for (int rp = 0; rp < 4; rp++) {
            float2 f0 = unpk(facp[ws][rp][0]);
            float2 f1 = unpk(facp[ws][rp][1]);
            float2 f2 = unpk(facp[ws][rp][2]);
            float2 f3 = unpk(facp[ws][rp][3]);
            int sA = s0 + ty*8 + 2*rp;
            float4 lo = {f0.x+ob4[0], f1.x+ob4[1], f2.x+ob4[2], f3.x+ob4[3]};
            float4 hi = {f0.y+ob4[0], f1.y+ob4[1], f2.y+ob4[2], f3.y+ob4[3]};
            *(float4*)&out[(((size_t)b*1024 + sA    )*8 + w)*64 + tx*4] = lo;
            *(float4*)&out[(((size_t)b*1024 + sA + 1)*8 + w)*64 + tx*4] = hi;
        }
    }
}

// ---------------- launch ----------------
extern "C" void kernel_launch(void* const* d_in, const int* in_sizes, int n_in,
                              void* d_out, int out_size) {
    const float* x        = (const float*)d_in[0];
    const float* pos      = (const float*)d_in[1];
    const float* strength = (const float*)d_in[2];
    const int*   embid    = (const int*)  d_in[3];
    const float* qw       = (const float*)d_in[4];
    const float* kw       = (const float*)d_in[5];
    const float* vw       = (const float*)d_in[6];
    const float* pw1      = (const float*)d_in[7];
    const float* pb1      = (const float*)d_in[8];
    const float* pw2      = (const float*)d_in[9];
    const float* pb2      = (const float*)d_in[10];
    const float* hw       = (const float*)d_in[11];
    // d_in[12] = head_b (cancels in softmax)
    const float* gate     = (const float*)d_in[13];
    const float* ow       = (const float*)d_in[14];
    const float* ob       = (const float*)d_in[15];
    const float* sw       = (const float*)d_in[16];
    const float* sb       = (const float*)d_in[17];
    float* out = (float*)d_out;

    const int attn_smem = (2*128*PIT + 128*128) * 4;   // 200704 B

    cudaFuncSetAttribute(k_proj, cudaFuncAttributeMaxDynamicSharedMemorySize, 86016);
    cudaFuncSetAttribute(k_attn, cudaFuncAttributeMaxDynamicSharedMemorySize, attn_smem);

    k_svec<<<1, 64>>>(strength, sw, sb);
    k_proj<<<dim3(128, 4), 256, 86016>>>(x, qw, kw, vw, embid);
    k_posb<<<16, 512>>>(pos, pw1, pb1, pw2, pb2, hw);
    k_attn<<<dim3(8, 16), 256, attn_smem>>>(gate, ow, ob, out);
}

// round 4
// speedup vs baseline: 1.4754x; 1.0040x over previous
#include <cuda_runtime.h>

typedef unsigned long long ULL;

// ---------------- f32x2 packed-FMA helpers ----------------
__device__ __forceinline__ void fma2(ULL &d, ULL a, ULL b) {
    asm("fma.rn.f32x2 %0, %1, %2, %0;" : "+l"(d) : "l"(a), "l"(b));
}
__device__ __forceinline__ void mul2(ULL &d, ULL b) {
    asm("mul.rn.f32x2 %0, %0, %1;" : "+l"(d) : "l"(b));
}
__device__ __forceinline__ ULL dup2(float f) {
    ULL r; asm("mov.b64 %0, {%1, %1};" : "=l"(r) : "f"(f)); return r;
}
__device__ __forceinline__ float2 unpk(ULL v) {
    float2 r; asm("mov.b64 {%0, %1}, %2;" : "=f"(r.x), "=f"(r.y) : "l"(v)); return r;
}

// ---------------- problem constants ----------------
#define BB   4
#define SS   1024
#define HH   4
#define HD   128
#define PIT  132     // smem pitch for 128-wide transposed tiles (132 % 32 == 4)

// ---------------- device scratch ----------------
__device__ float g_svec[64];
__device__ float g_q[BB*HH*SS*HD];
__device__ float g_k[BB*HH*SS*HD];
__device__ float g_v[BB*HH*SS*HD];
__device__ float g_pv[BB*HH*HD];       // pos_attn @ v (row-constant)

// ---------------- K0: strength projection ----------------
__global__ void k_svec(const float* __restrict__ strength,
                       const float* __restrict__ str_w,
                       const float* __restrict__ str_b) {
    int d = threadIdx.x;            // 64 threads
    float s = 0.f;
    #pragma unroll 8
    for (int i = 0; i < 512; i++) s += str_w[d*512 + i] * strength[i];
    g_svec[d] = s + str_b[d];
}

// ---------------- K1: q/k/v projections (f32x2) ----------------
__global__ __launch_bounds__(256) void k_proj(
    const float* __restrict__ x,
    const float* __restrict__ qw, const float* __restrict__ kw,
    const float* __restrict__ vw, const int* __restrict__ embid)
{
    extern __shared__ float sm[];
    float* xd = sm;            // [64 c][132] duplicated x
    float* qT = sm + 8448;     // [64 c][68]
    float* kT = sm + 12800;
    float* vT = sm + 17152;

    const int sblk = blockIdx.x;
    const int b    = blockIdx.y;
    const int s0   = sblk * 8;
    const int tid  = threadIdx.x;
    const int id   = embid[0];
    const float* qwb = qw + (size_t)id * 4096;
    const float* kwb = kw + (size_t)id * 4096;
    const float* vwb = vw + (size_t)id * 4096;

    for (int i = tid; i < 4096; i += 256) {
        int c = i >> 6, mm = i & 63;
        int sl = mm >> 3, w = mm & 7;
        float xv = x[(((size_t)b*64 + c)*1024 + (s0 + sl))*8 + w];
        xd[c*132 + 2*mm]     = xv;
        xd[c*132 + 2*mm + 1] = xv;
        int d2 = i >> 6, c2 = i & 63;
        qT[c2*68 + d2] = qwb[d2*64 + c2];
        kT[c2*68 + d2] = kwb[d2*64 + c2];
        vT[c2*68 + d2] = vwb[d2*64 + c2];
    }
    __syncthreads();

    const int tx = tid & 15, ty = tid >> 4;
    ULL aq[4][2] = {}, ak[4][2] = {}, av[4][2] = {};
    #pragma unroll 2
    for (int c = 0; c < 64; c++) {
        ulonglong2 qp = *(const ulonglong2*)(qT + c*68 + tx*4);
        ulonglong2 kp = *(const ulonglong2*)(kT + c*68 + tx*4);
        ulonglong2 vp = *(const ulonglong2*)(vT + c*68 + tx*4);
        ulonglong2 xa = *(const ulonglong2*)(xd + c*132 + ty*8);
        ulonglong2 xb = *(const ulonglong2*)(xd + c*132 + ty*8 + 4);
        fma2(aq[0][0], xa.x, qp.x); fma2(aq[0][1], xa.x, qp.y);
        fma2(aq[1][0], xa.y, qp.x); fma2(aq[1][1], xa.y, qp.y);
        fma2(aq[2][0], xb.x, qp.x); fma2(aq[2][1], xb.x, qp.y);
        fma2(aq[3][0], xb.y, qp.x); fma2(aq[3][1], xb.y, qp.y);
        fma2(ak[0][0], xa.x, kp.x); fma2(ak[0][1], xa.x, kp.y);
        fma2(ak[1][0], xa.y, kp.x); fma2(ak[1][1], xa.y, kp.y);
        fma2(ak[2][0], xb.x, kp.x); fma2(ak[2][1], xb.x, kp.y);
        fma2(ak[3][0], xb.y, kp.x); fma2(ak[3][1], xb.y, kp.y);
        fma2(av[0][0], xa.x, vp.x); fma2(av[0][1], xa.x, vp.y);
        fma2(av[1][0], xa.y, vp.x); fma2(av[1][1], xa.y, vp.y);
        fma2(av[2][0], xb.x, vp.x); fma2(av[2][1], xb.x, vp.y);
        fma2(av[3][0], xb.y, vp.x); fma2(av[3][1], xb.y, vp.y);
    }

    float sv[4];
    #pragma unroll
    for (int j = 0; j < 4; j++) sv[j] = g_svec[tx*4 + j];

    #pragma unroll
    for (int i = 0; i < 4; i++) {
        int mm = ty*4 + i;
        int sl = mm >> 3, w = mm & 7;
        int h = w >> 1;
        int jb = ((w & 1) << 6) + tx*4;
        size_t base = (((size_t)(b*4 + h)*1024 + (s0 + sl))*128 + jb);
        float2 a0, a1; float4 o;
        a0 = unpk(aq[i][0]); a1 = unpk(aq[i][1]);
        o.x = a0.x+sv[0]; o.y = a0.y+sv[1]; o.z = a1.x+sv[2]; o.w = a1.y+sv[3];
        *(float4*)&g_q[base] = o;
        a0 = unpk(ak[i][0]); a1 = unpk(ak[i][1]);
        o.x = a0.x+sv[0]; o.y = a0.y+sv[1]; o.z = a1.x+sv[2]; o.w = a1.y+sv[3];
        *(float4*)&g_k[base] = o;
        a0 = unpk(av[i][0]); a1 = unpk(av[i][1]);
        o.x = a0.x+sv[0]; o.y = a0.y+sv[1]; o.z = a1.x+sv[2]; o.w = a1.y+sv[3];
        *(float4*)&g_v[base] = o;
    }
}

// ---------------- K2: fused positional branch -> g_pv ----------------
// grid 16 (bh), 512 threads
__global__ __launch_bounds__(512) void k_posb(
    const float* __restrict__ pos,
    const float* __restrict__ w1, const float* __restrict__ b1,
    const float* __restrict__ w2, const float* __restrict__ b2,
    const float* __restrict__ hw)
{
    __shared__ float sn[1024];
    __shared__ float red[512];
    const int bh = blockIdx.x, b = bh >> 2, h = bh & 3;
    const int tid = threadIdx.x;

    float hwv[8];
    #pragma unroll
    for (int d = 0; d < 8; d++) hwv[d] = hw[h*8 + d];

    for (int s = tid; s < 1024; s += 512) {
        int idx = b*1024 + s;
        float p0 = pos[idx*3+0], p1 = pos[idx*3+1], p2 = pos[idx*3+2];
        float h1[3];
        #pragma unroll
        for (int j = 0; j < 3; j++)
            h1[j] = fmaxf(0.f, w1[j*3+0]*p0 + w1[j*3+1]*p1 + w1[j*3+2]*p2 + b1[j]);
        float a = 0.f;
        #pragma unroll
        for (int d = 0; d < 8; d++) {
            float ph = w2[d*3+0]*h1[0] + w2[d*3+1]*h1[1] + w2[d*3+2]*h1[2] + b2[d];
            a += ph * hwv[d];
        }
        sn[s] = -a;      // head_b cancels in softmax
    }
    __syncthreads();

    float mx = fmaxf(sn[tid], sn[tid + 512]);
    red[tid] = mx; __syncthreads();
    for (int s = 256; s > 0; s >>= 1) { if (tid < s) red[tid] = fmaxf(red[tid], red[tid+s]); __syncthreads(); }
    mx = red[0]; __syncthreads();

    float e0 = __expf(sn[tid] - mx), e1 = __expf(sn[tid+512] - mx);
    red[tid] = e0 + e1; __syncthreads();
    for (int s = 256; s > 0; s >>= 1) { if (tid < s) red[tid] += red[tid+s]; __syncthreads(); }
    float inv = 1.f / red[0];
    __syncthreads();
    sn[tid] = e0 * inv; sn[tid+512] = e1 * inv;
    __syncthreads();

    const int d = tid & 127, grp = tid >> 7;   // 4 groups of 256 t
    const float* vv = g_v + (size_t)bh*131072;
    float acc = 0.f;
    #pragma unroll 4
    for (int k = 0; k < 256; k++) {
        int t = grp*256 + k;
        acc += sn[t] * vv[(size_t)t*128 + d];
    }
    red[tid] = acc; __syncthreads();
    if (tid < 128)
        g_pv[bh*128 + d] = red[tid] + red[tid+128] + red[tid+256] + red[tid+384];
}

// ---------------- K3: flash attention, 128x128 tiles, 8x8/thread (f32x2) ----------------
// grid (8 stiles, 16 bh), 256 threads (tx 0..15 = keys/dcols, ty 0..15 = queries)
__global__ __launch_bounds__(256) void k_attn(
    const float* __restrict__ gate, const float* __restrict__ out_w,
    const float* __restrict__ out_b, float* __restrict__ out)
{
    extern __shared__ float sm[];
    float* qT  = sm;                 // [128 kk][PIT] q^T, pre-scaled
    float* kT  = sm + 128*PIT;       // [128 kk][PIT] k^T; reused as sPT [t][PIT] (swizzled)
    float* sV  = sm + 2*128*PIT;     // [128 t][128 d]
    // epilogue: oT = sm (128 d x PIT r, swizzled), owT = sm + 128*PIT (64x68)

    const int stile = blockIdx.x, bh = blockIdx.y;
    const int b = bh >> 2, h = bh & 3;
    const int s0 = stile * 128;
    const int tid = threadIdx.x, tx = tid & 15, ty = tid >> 4;

    const float* Q = g_q + (size_t)bh*131072;
    const float* K = g_k + (size_t)bh*131072;
    const float* V = g_v + (size_t)bh*131072;
    const float scale = 0.08838834764831845f;   // 1/sqrt(128)

    // stage Q^T (coalesced LDG over kk, 4-way-conflict STS: pitch%32==4, lane=kk)
    for (int i = tid; i < 16384; i += 256) {
        int kk = i & 127, r = i >> 7;
        qT[kk*PIT + r] = Q[(size_t)(s0 + r)*128 + kk] * scale;
    }

    float m[8], l[8];
    ULL o2[8][4];
    #pragma unroll
    for (int i = 0; i < 8; i++) {
        m[i] = -1e30f; l[i] = 0.f;
        #pragma unroll
        for (int j = 0; j < 4; j++) o2[i][j] = 0ULL;
    }

    for (int t0 = 0; t0 < 1024; t0 += 128) {
        __syncthreads();   // prev PV reads of sPT/sV done
        for (int i = tid; i < 16384; i += 256) {
            int kk = i & 127, c = i >> 7;
            kT[kk*PIT + c] = K[(size_t)(t0 + c)*128 + kk];
        }
        for (int i = tid; i < 4096; i += 256) {
            int t = i >> 5, d4 = i & 31;
            *(float4*)&sV[t*128 + d4*4] = *(const float4*)&V[(size_t)(t0 + t)*128 + d4*4];
        }
        __syncthreads();

        // ---- S = Qs @ K^T (128x128), 8x8 per thread ----
        ULL acc2[8][4];
        #pragma unroll
        for (int i = 0; i < 8; i++)
            #pragma unroll
            for (int j = 0; j < 4; j++) acc2[i][j] = 0ULL;

        #pragma unroll 2
        for (int kk = 0; kk < 128; kk++) {
            ulonglong2 kp0 = *(const ulonglong2*)(kT + kk*PIT + tx*8);      // 4 key pairs
            float4 qa = *(const float4*)(qT + kk*PIT + ty*8);
            float4 qb = *(const float4*)(qT + kk*PIT + ty*8 + 4);
            ULL qd[8];
            qd[0] = dup2(qa.x); qd[1] = dup2(qa.y); qd[2] = dup2(qa.z); qd[3] = dup2(qa.w);
            qd[4] = dup2(qb.x); qd[5] = dup2(qb.y); qd[6] = dup2(qb.z); qd[7] = dup2(qb.w);
            ulonglong2 kp1 = *(const ulonglong2*)(kT + kk*PIT + tx*8 + 4);
            #pragma unroll
            for (int i = 0; i < 8; i++) {
                fma2(acc2[i][0], qd[i], kp0.x);
                fma2(acc2[i][1], qd[i], kp0.y);
                fma2(acc2[i][2], qd[i], kp1.x);
                fma2(acc2[i][3], qd[i], kp1.y);
            }
        }
        __syncthreads();   // all kT reads done before P overwrites it

        // ---- online softmax + stage P^T into kT region (swizzled) ----
        float* sPT = kT;
        const int swzst = tx << 2;               // ((t>>3)&15)<<2, t=tx*8+jj
        #pragma unroll
        for (int i = 0; i < 8; i++) {
            float2 u0 = unpk(acc2[i][0]), u1 = unpk(acc2[i][1]);
            float2 u2 = unpk(acc2[i][2]), u3 = unpk(acc2[i][3]);
            float p[8] = {u0.x,u0.y,u1.x,u1.y,u2.x,u2.y,u3.x,u3.y};
            float tm = p[0];
            #pragma unroll
            for (int j = 1; j < 8; j++) tm = fmaxf(tm, p[j]);
            #pragma unroll
            for (int ofs = 1; ofs < 16; ofs <<= 1)
                tm = fmaxf(tm, __shfl_xor_sync(0xffffffffu, tm, ofs));
            float mn  = fmaxf(m[i], tm);
            float fac = __expf(m[i] - mn);
            m[i] = mn;
            float rs = 0.f;
            #pragma unroll
            for (int j = 0; j < 8; j++) { p[j] = __expf(p[j] - mn); rs += p[j]; }
            #pragma unroll
            for (int ofs = 1; ofs < 16; ofs <<= 1)
                rs += __shfl_xor_sync(0xffffffffu, rs, ofs);
            l[i] = l[i]*fac + rs;
            ULL fd = dup2(fac);
            #pragma unroll
            for (int j = 0; j < 4; j++) mul2(o2[i][j], fd);
            int col = (ty*8 + i) ^ swzst;
            #pragma unroll
            for (int j = 0; j < 8; j++)
                sPT[(tx*8 + j)*PIT + col] = p[j];
        }
        __syncthreads();

        // ---- O += P @ V ----
        #pragma unroll 2
        for (int tt = 0; tt < 128; tt++) {
            int swz = ((tt >> 3) & 15) << 2;
            float4 pa = *(const float4*)(sPT + tt*PIT + ((ty*8) ^ swz));
            float4 pb = *(const float4*)(sPT + tt*PIT + ((ty*8 + 4) ^ swz));
            ulonglong2 v0 = *(const ulonglong2*)(sV + tt*128 + tx*8);
            ulonglong2 v1 = *(const ulonglong2*)(sV + tt*128 + tx*8 + 4);
            ULL pd[8];
            pd[0] = dup2(pa.x); pd[1] = dup2(pa.y); pd[2] = dup2(pa.z); pd[3] = dup2(pa.w);
            pd[4] = dup2(pb.x); pd[5] = dup2(pb.y); pd[6] = dup2(pb.z); pd[7] = dup2(pb.w);
            #pragma unroll
            for (int i = 0; i < 8; i++) {
                fma2(o2[i][0], pd[i], v0.x);
                fma2(o2[i][1], pd[i], v0.y);
                fma2(o2[i][2], pd[i], v1.x);
                fma2(o2[i][3], pd[i], v1.y);
            }
        }
    }

    // ---- epilogue: normalize + gate-combine, fused out_w GEMM ----
    float gv  = 1.f / (1.f + __expf(-gate[h]));
    float omg = 1.f - gv;
    float pvv[8];
    #pragma unroll
    for (int j = 0; j < 8; j++) pvv[j] = g_pv[bh*128 + tx*8 + j];

    __syncthreads();   // PV reads done; reuse smem
    float* oT  = sm;              // [128 d][PIT r], swizzled cols: r ^ ((d>>3&15)<<2)
    float* owT = sm + 128*PIT;    // [64 cp][68 c]

    const int swzo = tx << 2;     // (d>>3)&15 = tx for d = tx*8+jj
    #pragma unroll
    for (int i = 0; i < 8; i++) {
        float invl = 1.f / l[i];
        float2 u0 = unpk(o2[i][0]), u1 = unpk(o2[i][1]);
        float2 u2 = unpk(o2[i][2]), u3 = unpk(o2[i][3]);
        float ov[8] = {u0.x,u0.y,u1.x,u1.y,u2.x,u2.y,u3.x,u3.y};
        int col = (ty*8 + i) ^ swzo;
        #pragma unroll
        for (int j = 0; j < 8; j++)
            oT[(tx*8 + j)*PIT + col] = omg * ov[j] * invl + gv * pvv[j];
    }
    for (int i = tid; i < 4096; i += 256) {
        int cp = i & 63, cc = i >> 6;
        owT[cp*68 + cc] = out_w[cc*64 + cp];
    }
    __syncthreads();

    // GEMM2: two 128x64x64 halves; row-pairs packed for f32x2
    ULL facp[2][4][4];
    #pragma unroll
    for (int ws = 0; ws < 2; ws++)
        #pragma unroll
        for (int rp = 0; rp < 4; rp++)
            #pragma unroll
            for (int j = 0; j < 4; j++) facp[ws][rp][j] = 0ULL;

    #pragma unroll 2
    for (int cp = 0; cp < 64; cp++) {
        int swz0 = ((cp >> 3) & 15) << 2;
        int swz1 = (((cp + 64) >> 3) & 15) << 2;
        const float* r0 = oT + cp*PIT;
        const float* r1 = oT + (cp + 64)*PIT;
        ulonglong2 oa = { *(const ULL*)(r0 + ((ty*8) ^ swz0)),
                          *(const ULL*)(r0 + ((ty*8 + 2) ^ swz0)) };
        ulonglong2 ob = { *(const ULL*)(r0 + ((ty*8 + 4) ^ swz0)),
                          *(const ULL*)(r0 + ((ty*8 + 6) ^ swz0)) };
        ulonglong2 oc = { *(const ULL*)(r1 + ((ty*8) ^ swz1)),
                          *(const ULL*)(r1 + ((ty*8 + 2) ^ swz1)) };
        ulonglong2 od = { *(const ULL*)(r1 + ((ty*8 + 4) ^ swz1)),
                          *(const ULL*)(r1 + ((ty*8 + 6) ^ swz1)) };
        float4 wf = *(const float4*)&owT[cp*68 + tx*4];
        ULL wd[4] = {dup2(wf.x), dup2(wf.y), dup2(wf.z), dup2(wf.w)};
        #pragma unroll
        for (int j = 0; j < 4; j++) {
            fma2(facp[0][0][j], oa.x, wd[j]);
            fma2(facp[0][1][j], oa.y, wd[j]);
            fma2(facp[0][2][j], ob.x, wd[j]);
            fma2(facp[0][3][j], ob.y, wd[j]);
            fma2(facp[1][0][j], oc.x, wd[j]);
            fma2(facp[1][1][j], oc.y, wd[j]);
            fma2(facp[1][2][j], od.x, wd[j]);
            fma2(facp[1][3][j], od.y, wd[j]);
        }
    }

    float ob4[4];
    #pragma unroll
    for (int j = 0; j < 4; j++) ob4[j] = out_b[tx*4 + j];

    #pragma unroll
    for (int ws = 0; ws < 2; ws++) {
        int w = h*2 + ws;
        #pragma unroll
        for (int rp = 0; rp < 4; rp++) {
            float2 f0 = unpk(facp[ws][rp][0]);
            float2 f1 = unpk(facp[ws][rp][1]);
            float2 f2 = unpk(facp[ws][rp][2]);
            float2 f3 = unpk(facp[ws][rp][3]);
            int sA = s0 + ty*8 + 2*rp;
            float4 lo = {f0.x+ob4[0], f1.x+ob4[1], f2.x+ob4[2], f3.x+ob4[3]};
            float4 hi = {f0.y+ob4[0], f1.y+ob4[1], f2.y+ob4[2], f3.y+ob4[3]};
            *(float4*)&out[(((size_t)b*1024 + sA    )*8 + w)*64 + tx*4] = lo;
            *(float4*)&out[(((size_t)b*1024 + sA + 1)*8 + w)*64 + tx*4] = hi;
        }
    }
}

// ---------------- launch ----------------
extern "C" void kernel_launch(void* const* d_in, const int* in_sizes, int n_in,
                              void* d_out, int out_size) {
    const float* x        = (const float*)d_in[0];
    const float* pos      = (const float*)d_in[1];
    const float* strength = (const float*)d_in[2];
    const int*   embid    = (const int*)  d_in[3];
    const float* qw       = (const float*)d_in[4];
    const float* kw       = (const float*)d_in[5];
    const float* vw       = (const float*)d_in[6];
    const float* pw1      = (const float*)d_in[7];
    const float* pb1      = (const float*)d_in[8];
    const float* pw2      = (const float*)d_in[9];
    const float* pb2      = (const float*)d_in[10];
    const float* hw       = (const float*)d_in[11];
    // d_in[12] = head_b (cancels in softmax)
    const float* gate     = (const float*)d_in[13];
    const float* ow       = (const float*)d_in[14];
    const float* ob       = (const float*)d_in[15];
    const float* sw       = (const float*)d_in[16];
    const float* sb       = (const float*)d_in[17];
    float* out = (float*)d_out;

    const int attn_smem = (2*128*PIT + 128*128) * 4;   // 200704 B

    cudaFuncSetAttribute(k_proj, cudaFuncAttributeMaxDynamicSharedMemorySize, 86016);
    cudaFuncSetAttribute(k_attn, cudaFuncAttributeMaxDynamicSharedMemorySize, attn_smem);

    k_svec<<<1, 64>>>(strength, sw, sb);
    k_proj<<<dim3(128, 4), 256, 86016>>>(x, qw, kw, vw, embid);
    k_posb<<<16, 512>>>(pos, pw1, pb1, pw2, pb2, hw);
    k_attn<<<dim3(8, 16), 256, attn_smem>>>(gate, ow, ob, out);
}

// round 5
// speedup vs baseline: 1.4775x; 1.0014x over previous
#include <cuda_runtime.h>

typedef unsigned long long ULL;

// ---------------- f32x2 packed-FMA helpers ----------------
__device__ __forceinline__ void fma2(ULL &d, ULL a, ULL b) {
    asm("fma.rn.f32x2 %0, %1, %2, %0;" : "+l"(d) : "l"(a), "l"(b));
}
__device__ __forceinline__ void mul2(ULL &d, ULL b) {
    asm("mul.rn.f32x2 %0, %0, %1;" : "+l"(d) : "l"(b));
}
__device__ __forceinline__ ULL dup2(float f) {
    ULL r; asm("mov.b64 %0, {%1, %1};" : "=l"(r) : "f"(f)); return r;
}
__device__ __forceinline__ float2 unpk(ULL v) {
    float2 r; asm("mov.b64 {%0, %1}, %2;" : "=f"(r.x), "=f"(r.y) : "l"(v)); return r;
}

// ---------------- problem constants ----------------
#define BB   4
#define SS   1024
#define HH   4
#define HD   128
#define PIT  132     // smem pitch for 128-wide transposed tiles (132 % 32 == 4)

// ---------------- device scratch ----------------
__device__ float g_svec[64];
__device__ float g_q[BB*HH*SS*HD];
__device__ float g_k[BB*HH*SS*HD];
__device__ float g_v[BB*HH*SS*HD];
__device__ float g_pv[BB*HH*HD];       // pos_attn @ v (row-constant)

// ---------------- K0: strength projection ----------------
__global__ void k_svec(const float* __restrict__ strength,
                       const float* __restrict__ str_w,
                       const float* __restrict__ str_b) {
    int d = threadIdx.x;            // 64 threads
    float s = 0.f;
    #pragma unroll 8
    for (int i = 0; i < 512; i++) s += str_w[d*512 + i] * strength[i];
    g_svec[d] = s + str_b[d];
}

// ---------------- K1: q/k/v projections (f32x2) ----------------
__global__ __launch_bounds__(256) void k_proj(
    const float* __restrict__ x,
    const float* __restrict__ qw, const float* __restrict__ kw,
    const float* __restrict__ vw, const int* __restrict__ embid)
{
    extern __shared__ float sm[];
    float* xd = sm;            // [64 c][132] duplicated x
    float* qT = sm + 8448;     // [64 c][68]
    float* kT = sm + 12800;
    float* vT = sm + 17152;

    const int sblk = blockIdx.x;
    const int b    = blockIdx.y;
    const int s0   = sblk * 8;
    const int tid  = threadIdx.x;
    const int id   = embid[0];
    const float* qwb = qw + (size_t)id * 4096;
    const float* kwb = kw + (size_t)id * 4096;
    const float* vwb = vw + (size_t)id * 4096;

    for (int i = tid; i < 4096; i += 256) {
        int c = i >> 6, mm = i & 63;
        int sl = mm >> 3, w = mm & 7;
        float xv = x[(((size_t)b*64 + c)*1024 + (s0 + sl))*8 + w];
        xd[c*132 + 2*mm]     = xv;
        xd[c*132 + 2*mm + 1] = xv;
        int d2 = i >> 6, c2 = i & 63;
        qT[c2*68 + d2] = qwb[d2*64 + c2];
        kT[c2*68 + d2] = kwb[d2*64 + c2];
        vT[c2*68 + d2] = vwb[d2*64 + c2];
    }
    __syncthreads();

    const int tx = tid & 15, ty = tid >> 4;
    ULL aq[4][2] = {}, ak[4][2] = {}, av[4][2] = {};
    #pragma unroll 2
    for (int c = 0; c < 64; c++) {
        ulonglong2 qp = *(const ulonglong2*)(qT + c*68 + tx*4);
        ulonglong2 kp = *(const ulonglong2*)(kT + c*68 + tx*4);
        ulonglong2 vp = *(const ulonglong2*)(vT + c*68 + tx*4);
        ulonglong2 xa = *(const ulonglong2*)(xd + c*132 + ty*8);
        ulonglong2 xb = *(const ulonglong2*)(xd + c*132 + ty*8 + 4);
        fma2(aq[0][0], xa.x, qp.x); fma2(aq[0][1], xa.x, qp.y);
        fma2(aq[1][0], xa.y, qp.x); fma2(aq[1][1], xa.y, qp.y);
        fma2(aq[2][0], xb.x, qp.x); fma2(aq[2][1], xb.x, qp.y);
        fma2(aq[3][0], xb.y, qp.x); fma2(aq[3][1], xb.y, qp.y);
        fma2(ak[0][0], xa.x, kp.x); fma2(ak[0][1], xa.x, kp.y);
        fma2(ak[1][0], xa.y, kp.x); fma2(ak[1][1], xa.y, kp.y);
        fma2(ak[2][0], xb.x, kp.x); fma2(ak[2][1], xb.x, kp.y);
        fma2(ak[3][0], xb.y, kp.x); fma2(ak[3][1], xb.y, kp.y);
        fma2(av[0][0], xa.x, vp.x); fma2(av[0][1], xa.x, vp.y);
        fma2(av[1][0], xa.y, vp.x); fma2(av[1][1], xa.y, vp.y);
        fma2(av[2][0], xb.x, vp.x); fma2(av[2][1], xb.x, vp.y);
        fma2(av[3][0], xb.y, vp.x); fma2(av[3][1], xb.y, vp.y);
    }

    float sv[4];
    #pragma unroll
    for (int j = 0; j < 4; j++) sv[j] = g_svec[tx*4 + j];

    #pragma unroll
    for (int i = 0; i < 4; i++) {
        int mm = ty*4 + i;
        int sl = mm >> 3, w = mm & 7;
        int h = w >> 1;
        int jb = ((w & 1) << 6) + tx*4;
        size_t base = (((size_t)(b*4 + h)*1024 + (s0 + sl))*128 + jb);
        float2 a0, a1; float4 o;
        a0 = unpk(aq[i][0]); a1 = unpk(aq[i][1]);
        o.x = a0.x+sv[0]; o.y = a0.y+sv[1]; o.z = a1.x+sv[2]; o.w = a1.y+sv[3];
        *(float4*)&g_q[base] = o;
        a0 = unpk(ak[i][0]); a1 = unpk(ak[i][1]);
        o.x = a0.x+sv[0]; o.y = a0.y+sv[1]; o.z = a1.x+sv[2]; o.w = a1.y+sv[3];
        *(float4*)&g_k[base] = o;
        a0 = unpk(av[i][0]); a1 = unpk(av[i][1]);
        o.x = a0.x+sv[0]; o.y = a0.y+sv[1]; o.z = a1.x+sv[2]; o.w = a1.y+sv[3];
        *(float4*)&g_v[base] = o;
    }
}

// ---------------- K2: fused positional branch -> g_pv ----------------
// grid 16 (bh), 512 threads
__global__ __launch_bounds__(512) void k_posb(
    const float* __restrict__ pos,
    const float* __restrict__ w1, const float* __restrict__ b1,
    const float* __restrict__ w2, const float* __restrict__ b2,
    const float* __restrict__ hw)
{
    __shared__ float sn[1024];
    __shared__ float red[512];
    const int bh = blockIdx.x, b = bh >> 2, h = bh & 3;
    const int tid = threadIdx.x;

    float hwv[8];
    #pragma unroll
    for (int d = 0; d < 8; d++) hwv[d] = hw[h*8 + d];

    for (int s = tid; s < 1024; s += 512) {
        int idx = b*1024 + s;
        float p0 = pos[idx*3+0], p1 = pos[idx*3+1], p2 = pos[idx*3+2];
        float h1[3];
        #pragma unroll
        for (int j = 0; j < 3; j++)
            h1[j] = fmaxf(0.f, w1[j*3+0]*p0 + w1[j*3+1]*p1 + w1[j*3+2]*p2 + b1[j]);
        float a = 0.f;
        #pragma unroll
        for (int d = 0; d < 8; d++) {
            float ph = w2[d*3+0]*h1[0] + w2[d*3+1]*h1[1] + w2[d*3+2]*h1[2] + b2[d];
            a += ph * hwv[d];
        }
        sn[s] = -a;      // head_b cancels in softmax
    }
    __syncthreads();

    float mx = fmaxf(sn[tid], sn[tid + 512]);
    red[tid] = mx; __syncthreads();
    for (int s = 256; s > 0; s >>= 1) { if (tid < s) red[tid] = fmaxf(red[tid], red[tid+s]); __syncthreads(); }
    mx = red[0]; __syncthreads();

    float e0 = __expf(sn[tid] - mx), e1 = __expf(sn[tid+512] - mx);
    red[tid] = e0 + e1; __syncthreads();
    for (int s = 256; s > 0; s >>= 1) { if (tid < s) red[tid] += red[tid+s]; __syncthreads(); }
    float inv = 1.f / red[0];
    __syncthreads();
    sn[tid] = e0 * inv; sn[tid+512] = e1 * inv;
    __syncthreads();

    const int d = tid & 127, grp = tid >> 7;   // 4 groups of 256 t
    const float* vv = g_v + (size_t)bh*131072;
    float acc = 0.f;
    #pragma unroll 4
    for (int k = 0; k < 256; k++) {
        int t = grp*256 + k;
        acc += sn[t] * vv[(size_t)t*128 + d];
    }
    red[tid] = acc; __syncthreads();
    if (tid < 128)
        g_pv[bh*128 + d] = red[tid] + red[tid+128] + red[tid+256] + red[tid+384];
}

// ---------------- K3: flash attention, 128x128 tiles, 8x8/thread (f32x2) ----------------
// grid (8 stiles, 16 bh), 256 threads (tx 0..15 = keys/dcols, ty 0..15 = queries)
__global__ __launch_bounds__(256) void k_attn(
    const float* __restrict__ gate, const float* __restrict__ out_w,
    const float* __restrict__ out_b, float* __restrict__ out)
{
    extern __shared__ float sm[];
    float* qT  = sm;                 // [128 kk][PIT] q^T, pre-scaled
    float* kT  = sm + 128*PIT;       // [128 kk][PIT] k^T; reused as sPT [t][PIT] (swizzled)
    float* sV  = sm + 2*128*PIT;     // [128 t][128 d]
    // epilogue: oT = sm (128 d x PIT r, swizzled), owT = sm + 128*PIT (64x68)

    const int stile = blockIdx.x, bh = blockIdx.y;
    const int b = bh >> 2, h = bh & 3;
    const int s0 = stile * 128;
    const int tid = threadIdx.x, tx = tid & 15, ty = tid >> 4;

    const float* Q = g_q + (size_t)bh*131072;
    const float* K = g_k + (size_t)bh*131072;
    const float* V = g_v + (size_t)bh*131072;
    const float scale = 0.08838834764831845f;   // 1/sqrt(128)

    // stage Q^T (coalesced LDG over kk, 4-way-conflict STS: pitch%32==4, lane=kk)
    for (int i = tid; i < 16384; i += 256) {
        int kk = i & 127, r = i >> 7;
        qT[kk*PIT + r] = Q[(size_t)(s0 + r)*128 + kk] * scale;
    }

    float m[8], l[8];
    ULL o2[8][4];
    #pragma unroll
    for (int i = 0; i < 8; i++) {
        m[i] = -1e30f; l[i] = 0.f;
        #pragma unroll
        for (int j = 0; j < 4; j++) o2[i][j] = 0ULL;
    }

    for (int t0 = 0; t0 < 1024; t0 += 128) {
        __syncthreads();   // prev PV reads of sPT/sV done
        for (int i = tid; i < 16384; i += 256) {
            int kk = i & 127, c = i >> 7;
            kT[kk*PIT + c] = K[(size_t)(t0 + c)*128 + kk];
        }
        for (int i = tid; i < 4096; i += 256) {
            int t = i >> 5, d4 = i & 31;
            *(float4*)&sV[t*128 + d4*4] = *(const float4*)&V[(size_t)(t0 + t)*128 + d4*4];
        }
        __syncthreads();

        // ---- S = Qs @ K^T (128x128), 8x8 per thread ----
        ULL acc2[8][4];
        #pragma unroll
        for (int i = 0; i < 8; i++)
            #pragma unroll
            for (int j = 0; j < 4; j++) acc2[i][j] = 0ULL;

        #pragma unroll 2
        for (int kk = 0; kk < 128; kk++) {
            ulonglong2 kp0 = *(const ulonglong2*)(kT + kk*PIT + tx*8);      // 4 key pairs
            float4 qa = *(const float4*)(qT + kk*PIT + ty*8);
            float4 qb = *(const float4*)(qT + kk*PIT + ty*8 + 4);
            ULL qd[8];
            qd[0] = dup2(qa.x); qd[1] = dup2(qa.y); qd[2] = dup2(qa.z); qd[3] = dup2(qa.w);
            qd[4] = dup2(qb.x); qd[5] = dup2(qb.y); qd[6] = dup2(qb.z); qd[7] = dup2(qb.w);
            ulonglong2 kp1 = *(const ulonglong2*)(kT + kk*PIT + tx*8 + 4);
            #pragma unroll
            for (int i = 0; i < 8; i++) {
                fma2(acc2[i][0], qd[i], kp0.x);
                fma2(acc2[i][1], qd[i], kp0.y);
                fma2(acc2[i][2], qd[i], kp1.x);
                fma2(acc2[i][3], qd[i], kp1.y);
            }
        }
        __syncthreads();   // all kT reads done before P overwrites it

        // ---- online softmax + stage P^T into kT region (swizzled) ----
        float* sPT = kT;
        const int swzst = tx << 2;               // ((t>>3)&15)<<2, t=tx*8+jj
        #pragma unroll
        for (int i = 0; i < 8; i++) {
            float2 u0 = unpk(acc2[i][0]), u1 = unpk(acc2[i][1]);
            float2 u2 = unpk(acc2[i][2]), u3 = unpk(acc2[i][3]);
            float p[8] = {u0.x,u0.y,u1.x,u1.y,u2.x,u2.y,u3.x,u3.y};
            float tm = p[0];
            #pragma unroll
            for (int j = 1; j < 8; j++) tm = fmaxf(tm, p[j]);
            #pragma unroll
            for (int ofs = 1; ofs < 16; ofs <<= 1)
                tm = fmaxf(tm, __shfl_xor_sync(0xffffffffu, tm, ofs));
            float mn  = fmaxf(m[i], tm);
            float fac = __expf(m[i] - mn);
            m[i] = mn;
            float rs = 0.f;
            #pragma unroll
            for (int j = 0; j < 8; j++) { p[j] = __expf(p[j] - mn); rs += p[j]; }
            #pragma unroll
            for (int ofs = 1; ofs < 16; ofs <<= 1)
                rs += __shfl_xor_sync(0xffffffffu, rs, ofs);
            l[i] = l[i]*fac + rs;
            ULL fd = dup2(fac);
            #pragma unroll
            for (int j = 0; j < 4; j++) mul2(o2[i][j], fd);
            int col = (ty*8 + i) ^ swzst;
            #pragma unroll
            for (int j = 0; j < 8; j++)
                sPT[(tx*8 + j)*PIT + col] = p[j];
        }
        __syncthreads();

        // ---- O += P @ V ----
        #pragma unroll 2
        for (int tt = 0; tt < 128; tt++) {
            int swz = ((tt >> 3) & 15) << 2;
            float4 pa = *(const float4*)(sPT + tt*PIT + ((ty*8) ^ swz));
            float4 pb = *(const float4*)(sPT + tt*PIT + ((ty*8 + 4) ^ swz));
            ulonglong2 v0 = *(const ulonglong2*)(sV + tt*128 + tx*8);
            ulonglong2 v1 = *(const ulonglong2*)(sV + tt*128 + tx*8 + 4);
            ULL pd[8];
            pd[0] = dup2(pa.x); pd[1] = dup2(pa.y); pd[2] = dup2(pa.z); pd[3] = dup2(pa.w);
            pd[4] = dup2(pb.x); pd[5] = dup2(pb.y); pd[6] = dup2(pb.z); pd[7] = dup2(pb.w);
            #pragma unroll
            for (int i = 0; i < 8; i++) {
                fma2(o2[i][0], pd[i], v0.x);
                fma2(o2[i][1], pd[i], v0.y);
                fma2(o2[i][2], pd[i], v1.x);
                fma2(o2[i][3], pd[i], v1.y);
            }
        }
    }

    // ---- epilogue: normalize + gate-combine, fused out_w GEMM ----
    float gv  = 1.f / (1.f + __expf(-gate[h]));
    float omg = 1.f - gv;
    float pvv[8];
    #pragma unroll
    for (int j = 0; j < 8; j++) pvv[j] = g_pv[bh*128 + tx*8 + j];

    __syncthreads();   // PV reads done; reuse smem
    float* oT  = sm;              // [128 d][PIT r], swizzled cols: r ^ ((d>>3&15)<<2)
    float* owT = sm + 128*PIT;    // [64 cp][68 c]

    const int swzo = tx << 2;     // (d>>3)&15 = tx for d = tx*8+jj
    #pragma unroll
    for (int i = 0; i < 8; i++) {
        float invl = 1.f / l[i];
        float2 u0 = unpk(o2[i][0]), u1 = unpk(o2[i][1]);
        float2 u2 = unpk(o2[i][2]), u3 = unpk(o2[i][3]);
        float ov[8] = {u0.x,u0.y,u1.x,u1.y,u2.x,u2.y,u3.x,u3.y};
        int col = (ty*8 + i) ^ swzo;
        #pragma unroll
        for (int j = 0; j < 8; j++)
            oT[(tx*8 + j)*PIT + col] = omg * ov[j] * invl + gv * pvv[j];
    }
    for (int i = tid; i < 4096; i += 256) {
        int cp = i & 63, cc = i >> 6;
        owT[cp*68 + cc] = out_w[cc*64 + cp];
    }
    __syncthreads();

    // GEMM2: two 128x64x64 halves; row-pairs packed for f32x2
    ULL facp[2][4][4];
    #pragma unroll
    for (int ws = 0; ws < 2; ws++)
        #pragma unroll
        for (int rp = 0; rp < 4; rp++)
            #pragma unroll
            for (int j = 0; j < 4; j++) facp[ws][rp][j] = 0ULL;

    #pragma unroll 2
    for (int cp = 0; cp < 64; cp++) {
        int swz0 = ((cp >> 3) & 15) << 2;
        int swz1 = (((cp + 64) >> 3) & 15) << 2;
        const float* r0 = oT + cp*PIT;
        const float* r1 = oT + (cp + 64)*PIT;
        ulonglong2 oa = { *(const ULL*)(r0 + ((ty*8) ^ swz0)),
                          *(const ULL*)(r0 + ((ty*8 + 2) ^ swz0)) };
        ulonglong2 ob = { *(const ULL*)(r0 + ((ty*8 + 4) ^ swz0)),
                          *(const ULL*)(r0 + ((ty*8 + 6) ^ swz0)) };
        ulonglong2 oc = { *(const ULL*)(r1 + ((ty*8) ^ swz1)),
                          *(const ULL*)(r1 + ((ty*8 + 2) ^ swz1)) };
        ulonglong2 od = { *(const ULL*)(r1 + ((ty*8 + 4) ^ swz1)),
                          *(const ULL*)(r1 + ((ty*8 + 6) ^ swz1)) };
        float4 wf = *(const float4*)&owT[cp*68 + tx*4];
        ULL wd[4] = {dup2(wf.x), dup2(wf.y), dup2(wf.z), dup2(wf.w)};
        #pragma unroll
        for (int j = 0; j < 4; j++) {
            fma2(facp[0][0][j], oa.x, wd[j]);
            fma2(facp[0][1][j], oa.y, wd[j]);
            fma2(facp[0][2][j], ob.x, wd[j]);
            fma2(facp[0][3][j], ob.y, wd[j]);
            fma2(facp[1][0][j], oc.x, wd[j]);
            fma2(facp[1][1][j], oc.y, wd[j]);
            fma2(facp[1][2][j], od.x, wd[j]);
            fma2(facp[1][3][j], od.y, wd[j]);
        }
    }

    float ob4[4];
    #pragma unroll
    for (int j = 0; j < 4; j++) ob4[j] = out_b[tx*4 + j];

    #pragma unroll
    for (int ws = 0; ws < 2; ws++) {
        int w = h*2 + ws;
        #pragma unroll
        for (int rp = 0; rp < 4; rp++) {
            float2 f0 = unpk(facp[ws][rp][0]);
            float2 f1 = unpk(facp[ws][rp][1]);
            float2 f2 = unpk(facp[ws][rp][2]);
            float2 f3 = unpk(facp[ws][rp][3]);
            int sA = s0 + ty*8 + 2*rp;
            float4 lo = {f0.x+ob4[0], f1.x+ob4[1], f2.x+ob4[2], f3.x+ob4[3]};
            float4 hi = {f0.y+ob4[0], f1.y+ob4[1], f2.y+ob4[2], f3.y+ob4[3]};
            *(float4*)&out[(((size_t)b*1024 + sA    )*8 + w)*64 + tx*4] = lo;
            *(float4*)&out[(((size_t)b*1024 + sA + 1)*8 + w)*64 + tx*4] = hi;
        }
    }
}

// ---------------- launch ----------------
extern "C" void kernel_launch(void* const* d_in, const int* in_sizes, int n_in,
                              void* d_out, int out_size) {
    const float* x        = (const float*)d_in[0];
    const float* pos      = (const float*)d_in[1];
    const float* strength = (const float*)d_in[2];
    const int*   embid    = (const int*)  d_in[3];
    const float* qw       = (const float*)d_in[4];
    const float* kw       = (const float*)d_in[5];
    const float* vw       = (const float*)d_in[6];
    const float* pw1      = (const float*)d_in[7];
    const float* pb1      = (const float*)d_in[8];
    const float* pw2      = (const float*)d_in[9];
    const float* pb2      = (const float*)d_in[10];
    const float* hw       = (const float*)d_in[11];
    // d_in[12] = head_b (cancels in softmax)
    const float* gate     = (const float*)d_in[13];
    const float* ow       = (const float*)d_in[14];
    const float* ob       = (const float*)d_in[15];
    const float* sw       = (const float*)d_in[16];
    const float* sb       = (const float*)d_in[17];
    float* out = (float*)d_out;

    const int attn_smem = (2*128*PIT + 128*128) * 4;   // 200704 B

    cudaFuncSetAttribute(k_proj, cudaFuncAttributeMaxDynamicSharedMemorySize, 86016);
    cudaFuncSetAttribute(k_attn, cudaFuncAttributeMaxDynamicSharedMemorySize, attn_smem);

    k_svec<<<1, 64>>>(strength, sw, sb);
    k_proj<<<dim3(128, 4), 256, 86016>>>(x, qw, kw, vw, embid);
    k_posb<<<16, 512>>>(pos, pw1, pb1, pw2, pb2, hw);
    k_attn<<<dim3(8, 16), 256, attn_smem>>>(gate, ow, ob, out);
}

// round 7
// speedup vs baseline: 4.0060x; 2.7114x over previous
#include <cuda_runtime.h>
#include <cuda_bf16.h>
#include <cstdint>

typedef unsigned long long ULL;

// ---------------- helpers ----------------
__device__ __forceinline__ uint32_t smem_u32(const void* p) {
    uint32_t a;
    asm("{ .reg .u64 t; cvta.to.shared.u64 t, %1; cvt.u32.u64 %0, t; }" : "=r"(a) : "l"(p));
    return a;
}
__device__ __forceinline__ void fma2(ULL &d, ULL a, ULL b) {
    asm("fma.rn.f32x2 %0, %1, %2, %0;" : "+l"(d) : "l"(a), "l"(b));
}
__device__ __forceinline__ ULL dup2(float f) {
    ULL r; asm("mov.b64 %0, {%1, %1};" : "=l"(r) : "f"(f)); return r;
}
__device__ __forceinline__ float2 unpk(ULL v) {
    float2 r; asm("mov.b64 {%0, %1}, %2;" : "=f"(r.x), "=f"(r.y) : "l"(v)); return r;
}
__device__ __forceinline__ uint32_t bf2pack(float a, float b) {
    __nv_bfloat162 t = __floats2bfloat162_rn(a, b);
    return *reinterpret_cast<uint32_t*>(&t);
}

#define LDSM4(r, addr) \
    asm volatile("ldmatrix.sync.aligned.m8n8.x4.shared.b16 {%0,%1,%2,%3}, [%4];" \
        : "=r"((r)[0]), "=r"((r)[1]), "=r"((r)[2]), "=r"((r)[3]) : "r"(addr))
#define LDSM4T(r, addr) \
    asm volatile("ldmatrix.sync.aligned.m8n8.x4.trans.shared.b16 {%0,%1,%2,%3}, [%4];" \
        : "=r"((r)[0]), "=r"((r)[1]), "=r"((r)[2]), "=r"((r)[3]) : "r"(addr))
#define MMA16816(c, a, b0, b1) \
    asm volatile("mma.sync.aligned.m16n8k16.row.col.f32.bf16.bf16.f32 " \
        "{%0,%1,%2,%3}, {%4,%5,%6,%7}, {%8,%9}, {%0,%1,%2,%3};" \
        : "+f"((c)[0]), "+f"((c)[1]), "+f"((c)[2]), "+f"((c)[3]) \
        : "r"((a)[0]), "r"((a)[1]), "r"((a)[2]), "r"((a)[3]), "r"(b0), "r"(b1))

// ---------------- problem constants ----------------
#define BB 4
#define SS 1024
#define HH 4
#define HD 128
#define PIT 132

// ---------------- device scratch ----------------
__device__ float g_svec[64];
__device__ __nv_bfloat16 g_qb[BB*HH*SS*HD];   // full q (y+s), pre-scaled
__device__ __nv_bfloat16 g_kb[BB*HH*SS*HD];   // y_k only (s removed — cancels in softmax)
__device__ __nv_bfloat16 g_vb[BB*HH*SS*HD];   // y_v only (s re-added in epilogue)
__device__ float g_v[BB*HH*SS*HD];            // full v fp32 (pos branch)
__device__ float g_pv[BB*HH*HD];

// ---------------- K0: strength projection ----------------
__global__ void k_svec(const float* __restrict__ strength,
                       const float* __restrict__ str_w,
                       const float* __restrict__ str_b) {
    int d = threadIdx.x;
    float s = 0.f;
    #pragma unroll 8
    for (int i = 0; i < 512; i++) s += str_w[d*512 + i] * strength[i];
    g_svec[d] = s + str_b[d];
}

// ---------------- K1: q/k/v projections ----------------
__global__ __launch_bounds__(256) void k_proj(
    const float* __restrict__ x,
    const float* __restrict__ qw, const float* __restrict__ kw,
    const float* __restrict__ vw, const int* __restrict__ embid)
{
    extern __shared__ float sm[];
    float* xd = sm;
    float* qT = sm + 8448;
    float* kT = sm + 12800;
    float* vT = sm + 17152;

    const int sblk = blockIdx.x, b = blockIdx.y;
    const int s0 = sblk * 8;
    const int tid = threadIdx.x;
    const int id = embid[0];
    const float* qwb = qw + (size_t)id * 4096;
    const float* kwb = kw + (size_t)id * 4096;
    const float* vwb = vw + (size_t)id * 4096;

    for (int i = tid; i < 4096; i += 256) {
        int c = i >> 6, mm = i & 63;
        int sl = mm >> 3, w = mm & 7;
        float xv = x[(((size_t)b*64 + c)*1024 + (s0 + sl))*8 + w];
        xd[c*132 + 2*mm] = xv;
        xd[c*132 + 2*mm + 1] = xv;
        int d2 = i >> 6, c2 = i & 63;
        qT[c2*68 + d2] = qwb[d2*64 + c2];
        kT[c2*68 + d2] = kwb[d2*64 + c2];
        vT[c2*68 + d2] = vwb[d2*64 + c2];
    }
    __syncthreads();

    const int tx = tid & 15, ty = tid >> 4;
    ULL aq[4][2] = {}, ak[4][2] = {}, av[4][2] = {};
    #pragma unroll 2
    for (int c = 0; c < 64; c++) {
        ulonglong2 qp = *(const ulonglong2*)(qT + c*68 + tx*4);
        ulonglong2 kp = *(const ulonglong2*)(kT + c*68 + tx*4);
        ulonglong2 vp = *(const ulonglong2*)(vT + c*68 + tx*4);
        ulonglong2 xa = *(const ulonglong2*)(xd + c*132 + ty*8);
        ulonglong2 xb = *(const ulonglong2*)(xd + c*132 + ty*8 + 4);
        fma2(aq[0][0], xa.x, qp.x); fma2(aq[0][1], xa.x, qp.y);
        fma2(aq[1][0], xa.y, qp.x); fma2(aq[1][1], xa.y, qp.y);
        fma2(aq[2][0], xb.x, qp.x); fma2(aq[2][1], xb.x, qp.y);
        fma2(aq[3][0], xb.y, qp.x); fma2(aq[3][1], xb.y, qp.y);
        fma2(ak[0][0], xa.x, kp.x); fma2(ak[0][1], xa.x, kp.y);
        fma2(ak[1][0], xa.y, kp.x); fma2(ak[1][1], xa.y, kp.y);
        fma2(ak[2][0], xb.x, kp.x); fma2(ak[2][1], xb.x, kp.y);
        fma2(ak[3][0], xb.y, kp.x); fma2(ak[3][1], xb.y, kp.y);
        fma2(av[0][0], xa.x, vp.x); fma2(av[0][1], xa.x, vp.y);
        fma2(av[1][0], xa.y, vp.x); fma2(av[1][1], xa.y, vp.y);
        fma2(av[2][0], xb.x, vp.x); fma2(av[2][1], xb.x, vp.y);
        fma2(av[3][0], xb.y, vp.x); fma2(av[3][1], xb.y, vp.y);
    }

    float sv[4];
    #pragma unroll
    for (int j = 0; j < 4; j++) sv[j] = g_svec[tx*4 + j];
    const float SC = 0.08838834764831845f;   // 1/sqrt(128)

    #pragma unroll
    for (int i = 0; i < 4; i++) {
        int mm = ty*4 + i;
        int sl = mm >> 3, w = mm & 7;
        int h = w >> 1;
        int jb = ((w & 1) << 6) + tx*4;
        int s = s0 + sl;
        int bh = b*4 + h;
        size_t base = ((size_t)bh*1024 + s)*128 + jb;
        float2 a0, a1; uint2 u;
        // q: full (y+s), pre-scaled
        a0 = unpk(aq[i][0]); a1 = unpk(aq[i][1]);
        u.x = bf2pack((a0.x+sv[0])*SC, (a0.y+sv[1])*SC);
        u.y = bf2pack((a1.x+sv[2])*SC, (a1.y+sv[3])*SC);
        *(uint2*)&g_qb[base] = u;
        // k: y only
        a0 = unpk(ak[i][0]); a1 = unpk(ak[i][1]);
        u.x = bf2pack(a0.x, a0.y); u.y = bf2pack(a1.x, a1.y);
        *(uint2*)&g_kb[base] = u;
        // v: y bf16 + full fp32
        a0 = unpk(av[i][0]); a1 = unpk(av[i][1]);
        u.x = bf2pack(a0.x, a0.y); u.y = bf2pack(a1.x, a1.y);
        *(uint2*)&g_vb[base] = u;
        *(float4*)&g_v[base] = make_float4(a0.x+sv[0], a0.y+sv[1], a1.x+sv[2], a1.y+sv[3]);
    }
}

// ---------------- K2: positional branch -> g_pv ----------------
__global__ __launch_bounds__(512) void k_posb(
    const float* __restrict__ pos,
    const float* __restrict__ w1, const float* __restrict__ b1,
    const float* __restrict__ w2, const float* __restrict__ b2,
    const float* __restrict__ hw)
{
    __shared__ float sn[1024];
    __shared__ float red[512];
    const int bh = blockIdx.x, b = bh >> 2, h = bh & 3;
    const int tid = threadIdx.x;

    float hwv[8];
    #pragma unroll
    for (int d = 0; d < 8; d++) hwv[d] = hw[h*8 + d];

    for (int s = tid; s < 1024; s += 512) {
        int idx = b*1024 + s;
        float p0 = pos[idx*3+0], p1 = pos[idx*3+1], p2 = pos[idx*3+2];
        float h1[3];
        #pragma unroll
        for (int j = 0; j < 3; j++)
            h1[j] = fmaxf(0.f, w1[j*3+0]*p0 + w1[j*3+1]*p1 + w1[j*3+2]*p2 + b1[j]);
        float a = 0.f;
        #pragma unroll
        for (int d = 0; d < 8; d++) {
            float ph = w2[d*3+0]*h1[0] + w2[d*3+1]*h1[1] + w2[d*3+2]*h1[2] + b2[d];
            a += ph * hwv[d];
        }
        sn[s] = -a;
    }
    __syncthreads();

    float mx = fmaxf(sn[tid], sn[tid + 512]);
    red[tid] = mx; __syncthreads();
    for (int s = 256; s > 0; s >>= 1) { if (tid < s) red[tid] = fmaxf(red[tid], red[tid+s]); __syncthreads(); }
    mx = red[0]; __syncthreads();

    float e0 = __expf(sn[tid] - mx), e1 = __expf(sn[tid+512] - mx);
    red[tid] = e0 + e1; __syncthreads();
    for (int s = 256; s > 0; s >>= 1) { if (tid < s) red[tid] += red[tid+s]; __syncthreads(); }
    float inv = 1.f / red[0];
    __syncthreads();
    sn[tid] = e0 * inv; sn[tid+512] = e1 * inv;
    __syncthreads();

    const int d = tid & 127, grp = tid >> 7;
    const float* vv = g_v + (size_t)bh*131072;
    float acc = 0.f;
    #pragma unroll 4
    for (int k = 0; k < 256; k++) {
        int t = grp*256 + k;
        acc += sn[t] * vv[(size_t)t*128 + d];
    }
    red[tid] = acc; __syncthreads();
    if (tid < 128)
        g_pv[bh*128 + d] = red[tid] + red[tid+128] + red[tid+256] + red[tid+384];
}

// ---------------- K3: bf16 mma.sync flash attention ----------------
// grid (8 stiles, 16 bh), 256 threads / 8 warps; warp owns 16 q-rows.
// smem: swizzled bf16 tiles [row][16 chunks of 16B], chunk ^= row&7
#define SQO 0
#define SKO 32768
#define SVO 65536
#define SADD 98304
#define ATTN_SMEM 98816

__global__ __launch_bounds__(256) void k_attn(
    const float* __restrict__ gate, const float* __restrict__ out_w,
    const float* __restrict__ out_b, float* __restrict__ out)
{
    extern __shared__ char smc[];
    float* smf = (float*)smc;
    const uint32_t sb = smem_u32(smc);
    const int stile = blockIdx.x, bh = blockIdx.y;
    const int b = bh >> 2, h = bh & 3;
    const int s0 = stile * 128;
    const int tid = threadIdx.x, wid = tid >> 5, l = tid & 31;
    const int lr = l & 7, lb8 = (l >> 3) & 1, lb16 = l >> 4;

    const float gv  = 1.f / (1.f + __expf(-gate[h]));
    const float omg = 1.f - gv;
    float* sAdd = (float*)(smc + SADD);
    if (tid < 128) sAdd[tid] = omg * g_svec[tid & 63] + gv * g_pv[bh*128 + tid];

    // ---- stage Q (once) ----
    const __nv_bfloat16* Qb = g_qb + (size_t)bh*131072 + (size_t)s0*128;
    for (int i = tid; i < 2048; i += 256) {
        int r = i >> 4, cc = i & 15;
        *(uint4*)(smc + SQO + r*256 + ((cc ^ (r & 7)) << 4)) =
            *(const uint4*)(Qb + (size_t)r*128 + cc*8);
    }
    __syncthreads();

    // ---- cache Q A-frags (m16k16 per kstep) ----
    const int mb = wid * 16;
    const int arow = mb + lr + (lb8 << 3);
    const uint32_t aBase = sb + SQO + arow*256;
    uint32_t aq[8][4];
    #pragma unroll
    for (int ks = 0; ks < 8; ks++) {
        uint32_t ad = aBase + (((uint32_t)((ks << 1) | lb16) ^ (uint32_t)lr) << 4);
        LDSM4(aq[ks], ad);
    }

    float oacc[16][4];
    #pragma unroll
    for (int i = 0; i < 16; i++)
        #pragma unroll
        for (int j = 0; j < 4; j++) oacc[i][j] = 0.f;
    float lsum0 = 0.f, lsum1 = 0.f;

    const __nv_bfloat16* Kb = g_kb + (size_t)bh*131072;
    const __nv_bfloat16* Vb = g_vb + (size_t)bh*131072;
    const uint32_t kRowB = sb + SKO + (uint32_t)(lr + (lb16 << 3))*256;
    const uint32_t vRowB = sb + SVO + (uint32_t)(lr + (lb8  << 3))*256;

    for (int c = 0; c < 8; c++) {
        __syncthreads();
        const int t0 = c * 128;
        for (int i = tid; i < 2048; i += 256) {
            int r = i >> 4, cc = i & 15;
            uint32_t sw = (uint32_t)(r*256 + ((cc ^ (r & 7)) << 4));
            *(uint4*)(smc + SKO + sw) = *(const uint4*)(Kb + (size_t)(t0 + r)*128 + cc*8);
            *(uint4*)(smc + SVO + sw) = *(const uint4*)(Vb + (size_t)(t0 + r)*128 + cc*8);
        }
        __syncthreads();

        // ---- S = Q @ K^T (128 rows x 128 keys per CTA; warp does m16) ----
        float sacc[16][4];
        #pragma unroll
        for (int i = 0; i < 16; i++)
            #pragma unroll
            for (int j = 0; j < 4; j++) sacc[i][j] = 0.f;

        #pragma unroll
        for (int ks = 0; ks < 8; ks++) {
            #pragma unroll
            for (int n2 = 0; n2 < 8; n2++) {
                uint32_t bfr[4];
                uint32_t ad = kRowB + (uint32_t)n2*4096
                            + (((uint32_t)((ks << 1) | lb8) ^ (uint32_t)lr) << 4);
                LDSM4(bfr, ad);
                MMA16816(sacc[2*n2],     aq[ks], bfr[0], bfr[1]);
                MMA16816(sacc[2*n2 + 1], aq[ks], bfr[2], bfr[3]);
            }
        }

        // ---- exp (C=0; row-const q·s cancelled analytically) -> P A-frags ----
        uint32_t pf[8][4];
        #pragma unroll
        for (int nt = 0; nt < 16; nt++) {
            float e0 = __expf(sacc[nt][0]);
            float e1 = __expf(sacc[nt][1]);
            float e2 = __expf(sacc[nt][2]);
            float e3 = __expf(sacc[nt][3]);
            lsum0 += e0 + e1;
            lsum1 += e2 + e3;
            pf[nt >> 1][(nt & 1)*2]     = bf2pack(e0, e1);
            pf[nt >> 1][(nt & 1)*2 + 1] = bf2pack(e2, e3);
        }

        // ---- O += P @ V ----
        #pragma unroll
        for (int np = 0; np < 8; np++) {
            #pragma unroll
            for (int ks = 0; ks < 8; ks++) {
                uint32_t bfr[4];
                uint32_t ad = vRowB + (uint32_t)ks*4096
                            + (((uint32_t)((np << 1) | lb16) ^ (uint32_t)lr) << 4);
                LDSM4T(bfr, ad);
                MMA16816(oacc[2*np],     pf[ks], bfr[0], bfr[1]);
                MMA16816(oacc[2*np + 1], pf[ks], bfr[2], bfr[3]);
            }
        }
    }

    // ---- row sums (quad reduce) ----
    lsum0 += __shfl_xor_sync(0xffffffffu, lsum0, 1);
    lsum0 += __shfl_xor_sync(0xffffffffu, lsum0, 2);
    lsum1 += __shfl_xor_sync(0xffffffffu, lsum1, 1);
    lsum1 += __shfl_xor_sync(0xffffffffu, lsum1, 2);
    const float inv0 = omg / lsum0;
    const float inv1 = omg / lsum1;

    __syncthreads();   // done with sQ/sK/sV; reuse as oT/owT
    float* oT  = smf;              // [128 d][PIT r], col = r ^ (((d>>3)&15)<<2)
    float* owT = smf + 128*PIT;

    const int r0r = mb + (l >> 2), r1r = r0r + 8;
    #pragma unroll
    for (int nt = 0; nt < 16; nt++) {
        int d0 = 8*nt + 2*(l & 3);
        int sw = nt << 2;   // ((d0>>3)&15)<<2
        oT[d0*PIT     + (r0r ^ sw)] = oacc[nt][0]*inv0 + sAdd[d0];
        oT[(d0+1)*PIT + (r0r ^ sw)] = oacc[nt][1]*inv0 + sAdd[d0+1];
        oT[d0*PIT     + (r1r ^ sw)] = oacc[nt][2]*inv1 + sAdd[d0];
        oT[(d0+1)*PIT + (r1r ^ sw)] = oacc[nt][3]*inv1 + sAdd[d0+1];
    }
    for (int i = tid; i < 4096; i += 256) {
        int cp = i & 63, cc = i >> 6;
        owT[cp*68 + cc] = out_w[cc*64 + cp];
    }
    __syncthreads();

    // ---- GEMM2: out = oT @ out_w^T + out_b (fp32x2) ----
    const int tx = tid & 15, ty = tid >> 4;
    ULL facp[2][4][4];
    #pragma unroll
    for (int ws = 0; ws < 2; ws++)
        #pragma unroll
        for (int rp = 0; rp < 4; rp++)
            #pragma unroll
            for (int j = 0; j < 4; j++) facp[ws][rp][j] = 0ULL;

    #pragma unroll 2
    for (int cp = 0; cp < 64; cp++) {
        int swz0 = ((cp >> 3) & 15) << 2;
        int swz1 = (((cp + 64) >> 3) & 15) << 2;
        const float* r0 = oT + cp*PIT;
        const float* r1 = oT + (cp + 64)*PIT;
        ulonglong2 oa = { *(const ULL*)(r0 + ((ty*8) ^ swz0)),
                          *(const ULL*)(r0 + ((ty*8 + 2) ^ swz0)) };
        ulonglong2 ob = { *(const ULL*)(r0 + ((ty*8 + 4) ^ swz0)),
                          *(const ULL*)(r0 + ((ty*8 + 6) ^ swz0)) };
        ulonglong2 oc = { *(const ULL*)(r1 + ((ty*8) ^ swz1)),
                          *(const ULL*)(r1 + ((ty*8 + 2) ^ swz1)) };
        ulonglong2 od = { *(const ULL*)(r1 + ((ty*8 + 4) ^ swz1)),
                          *(const ULL*)(r1 + ((ty*8 + 6) ^ swz1)) };
        float4 wf = *(const float4*)&owT[cp*68 + tx*4];
        ULL wd[4] = {dup2(wf.x), dup2(wf.y), dup2(wf.z), dup2(wf.w)};
        #pragma unroll
        for (int j = 0; j < 4; j++) {
            fma2(facp[0][0][j], oa.x, wd[j]);
            fma2(facp[0][1][j], oa.y, wd[j]);
            fma2(facp[0][2][j], ob.x, wd[j]);
            fma2(facp[0][3][j], ob.y, wd[j]);
            fma2(facp[1][0][j], oc.x, wd[j]);
            fma2(facp[1][1][j], oc.y, wd[j]);
            fma2(facp[1][2][j], od.x, wd[j]);
            fma2(facp[1][3][j], od.y, wd[j]);
        }
    }

    float ob4[4];
    #pragma unroll
    for (int j = 0; j < 4; j++) ob4[j] = out_b[tx*4 + j];

    #pragma unroll
    for (int ws = 0; ws < 2; ws++) {
        int w = h*2 + ws;
        #pragma unroll
        for (int rp = 0; rp < 4; rp++) {
            float2 f0 = unpk(facp[ws][rp][0]);
            float2 f1 = unpk(facp[ws][rp][1]);
            float2 f2 = unpk(facp[ws][rp][2]);
            float2 f3 = unpk(facp[ws][rp][3]);
            int sA = s0 + ty*8 + 2*rp;
            float4 lo = {f0.x+ob4[0], f1.x+ob4[1], f2.x+ob4[2], f3.x+ob4[3]};
            float4 hi = {f0.y+ob4[0], f1.y+ob4[1], f2.y+ob4[2], f3.y+ob4[3]};
            *(float4*)&out[(((size_t)b*1024 + sA    )*8 + w)*64 + tx*4] = lo;
            *(float4*)&out[(((size_t)b*1024 + sA + 1)*8 + w)*64 + tx*4] = hi;
        }
    }
}

// ---------------- launch ----------------
extern "C" void kernel_launch(void* const* d_in, const int* in_sizes, int n_in,
                              void* d_out, int out_size) {
    const float* x        = (const float*)d_in[0];
    const float* pos      = (const float*)d_in[1];
    const float* strength = (const float*)d_in[2];
    const int*   embid    = (const int*)  d_in[3];
    const float* qw       = (const float*)d_in[4];
    const float* kw       = (const float*)d_in[5];
    const float* vw       = (const float*)d_in[6];
    const float* pw1      = (const float*)d_in[7];
    const float* pb1      = (const float*)d_in[8];
    const float* pw2      = (const float*)d_in[9];
    const float* pb2      = (const float*)d_in[10];
    const float* hw       = (const float*)d_in[11];
    // d_in[12] = head_b (cancels in softmax)
    const float* gate     = (const float*)d_in[13];
    const float* ow       = (const float*)d_in[14];
    const float* ob       = (const float*)d_in[15];
    const float* sw       = (const float*)d_in[16];
    const float* sb       = (const float*)d_in[17];
    float* out = (float*)d_out;

    cudaFuncSetAttribute(k_proj, cudaFuncAttributeMaxDynamicSharedMemorySize, 86016);
    cudaFuncSetAttribute(k_attn, cudaFuncAttributeMaxDynamicSharedMemorySize, ATTN_SMEM);

    k_svec<<<1, 64>>>(strength, sw, sb);
    k_proj<<<dim3(128, 4), 256, 86016>>>(x, qw, kw, vw, embid);
    k_posb<<<16, 512>>>(pos, pw1, pb1, pw2, pb2, hw);
    k_attn<<<dim3(8, 16), 256, ATTN_SMEM>>>(gate, ow, ob, out);
}

// round 8
// speedup vs baseline: 5.2203x; 1.3031x over previous
#include <cuda_runtime.h>
#include <cuda_bf16.h>
#include <cstdint>

typedef unsigned long long ULL;

// ---------------- helpers ----------------
__device__ __forceinline__ uint32_t smem_u32(const void* p) {
    uint32_t a;
    asm("{ .reg .u64 t; cvta.to.shared.u64 t, %1; cvt.u32.u64 %0, t; }" : "=r"(a) : "l"(p));
    return a;
}
__device__ __forceinline__ void fma2(ULL &d, ULL a, ULL b) {
    asm("fma.rn.f32x2 %0, %1, %2, %0;" : "+l"(d) : "l"(a), "l"(b));
}
__device__ __forceinline__ ULL dup2(float f) {
    ULL r; asm("mov.b64 %0, {%1, %1};" : "=l"(r) : "f"(f)); return r;
}
__device__ __forceinline__ float2 unpk(ULL v) {
    float2 r; asm("mov.b64 {%0, %1}, %2;" : "=f"(r.x), "=f"(r.y) : "l"(v)); return r;
}
__device__ __forceinline__ uint32_t bf2pack(float a, float b) {
    __nv_bfloat162 t = __floats2bfloat162_rn(a, b);
    return *reinterpret_cast<uint32_t*>(&t);
}

#define LDSM4(r, addr) \
    asm volatile("ldmatrix.sync.aligned.m8n8.x4.shared.b16 {%0,%1,%2,%3}, [%4];" \
        : "=r"((r)[0]), "=r"((r)[1]), "=r"((r)[2]), "=r"((r)[3]) : "r"(addr))
#define LDSM4T(r, addr) \
    asm volatile("ldmatrix.sync.aligned.m8n8.x4.trans.shared.b16 {%0,%1,%2,%3}, [%4];" \
        : "=r"((r)[0]), "=r"((r)[1]), "=r"((r)[2]), "=r"((r)[3]) : "r"(addr))
#define MMA16816(c, a, b0, b1) \
    asm volatile("mma.sync.aligned.m16n8k16.row.col.f32.bf16.bf16.f32 " \
        "{%0,%1,%2,%3}, {%4,%5,%6,%7}, {%8,%9}, {%0,%1,%2,%3};" \
        : "+f"((c)[0]), "+f"((c)[1]), "+f"((c)[2]), "+f"((c)[3]) \
        : "r"((a)[0]), "r"((a)[1]), "r"((a)[2]), "r"((a)[3]), "r"(b0), "r"(b1))

#define CP_ASYNC16(dst, src) \
    asm volatile("cp.async.cg.shared.global [%0], [%1], 16;" :: "r"(dst), "l"(src) : "memory")
#define CP_COMMIT() asm volatile("cp.async.commit_group;" ::: "memory")
#define CP_WAIT1()  asm volatile("cp.async.wait_group 1;" ::: "memory")
#define CP_WAIT0()  asm volatile("cp.async.wait_group 0;" ::: "memory")

// ---------------- problem constants ----------------
#define BB 4
#define SS 1024
#define HH 4
#define HD 128
#define PIT 132

// ---------------- device scratch ----------------
__device__ float g_svec[64];
__device__ __nv_bfloat16 g_qb[BB*HH*SS*HD];   // full q (y+s), pre-scaled
__device__ __nv_bfloat16 g_kb[BB*HH*SS*HD];   // y_k only (s cancels in softmax)
__device__ __nv_bfloat16 g_vb[BB*HH*SS*HD];   // y_v only (s re-added in epilogue)
__device__ float g_v[BB*HH*SS*HD];            // full v fp32 (pos branch)
__device__ float g_pw[BB*HH*SS];              // normalized pos softmax weights
__device__ float g_pvpart[16*8*128];          // partial pv

// ---------------- K0: pos softmax weights (blocks 0..15) + svec (block 16) ----------------
__global__ __launch_bounds__(512) void k_posb1(
    const float* __restrict__ pos,
    const float* __restrict__ w1, const float* __restrict__ b1,
    const float* __restrict__ w2, const float* __restrict__ b2,
    const float* __restrict__ hw,
    const float* __restrict__ strength,
    const float* __restrict__ str_w, const float* __restrict__ str_b)
{
    const int tid = threadIdx.x;
    if (blockIdx.x == 16) {       // strength projection
        int d = tid >> 3, seg = tid & 7;
        const float* wrow = str_w + d*512 + seg*64;
        const float* st   = strength + seg*64;
        float s = 0.f;
        #pragma unroll 16
        for (int j = 0; j < 64; j++) s += wrow[j] * st[j];
        s += __shfl_xor_sync(0xffffffffu, s, 1);
        s += __shfl_xor_sync(0xffffffffu, s, 2);
        s += __shfl_xor_sync(0xffffffffu, s, 4);
        if (seg == 0) g_svec[d] = s + str_b[d];
        return;
    }

    __shared__ float sn[1024];
    __shared__ float red[512];
    const int bh = blockIdx.x, b = bh >> 2, h = bh & 3;

    float hwv[8];
    #pragma unroll
    for (int d = 0; d < 8; d++) hwv[d] = hw[h*8 + d];

    for (int s = tid; s < 1024; s += 512) {
        int idx = b*1024 + s;
        float p0 = pos[idx*3+0], p1 = pos[idx*3+1], p2 = pos[idx*3+2];
        float h1[3];
        #pragma unroll
        for (int j = 0; j < 3; j++)
            h1[j] = fmaxf(0.f, w1[j*3+0]*p0 + w1[j*3+1]*p1 + w1[j*3+2]*p2 + b1[j]);
        float a = 0.f;
        #pragma unroll
        for (int d = 0; d < 8; d++) {
            float ph = w2[d*3+0]*h1[0] + w2[d*3+1]*h1[1] + w2[d*3+2]*h1[2] + b2[d];
            a += ph * hwv[d];
        }
        sn[s] = -a;     // head_b cancels in softmax
    }
    __syncthreads();

    float mx = fmaxf(sn[tid], sn[tid + 512]);
    red[tid] = mx; __syncthreads();
    for (int s = 256; s > 0; s >>= 1) { if (tid < s) red[tid] = fmaxf(red[tid], red[tid+s]); __syncthreads(); }
    mx = red[0]; __syncthreads();

    float e0 = __expf(sn[tid] - mx), e1 = __expf(sn[tid+512] - mx);
    red[tid] = e0 + e1; __syncthreads();
    for (int s = 256; s > 0; s >>= 1) { if (tid < s) red[tid] += red[tid+s]; __syncthreads(); }
    float inv = 1.f / red[0];

    g_pw[(size_t)bh*1024 + tid]       = e0 * inv;
    g_pw[(size_t)bh*1024 + tid + 512] = e1 * inv;
}

// ---------------- K1: q/k/v projections ----------------
__global__ __launch_bounds__(256) void k_proj(
    const float* __restrict__ x,
    const float* __restrict__ qw, const float* __restrict__ kw,
    const float* __restrict__ vw, const int* __restrict__ embid)
{
    extern __shared__ float sm[];
    float* xd = sm;
    float* qT = sm + 8448;
    float* kT = sm + 12800;
    float* vT = sm + 17152;

    const int sblk = blockIdx.x, b = blockIdx.y;
    const int s0 = sblk * 8;
    const int tid = threadIdx.x;
    const int id = embid[0];
    const float* qwb = qw + (size_t)id * 4096;
    const float* kwb = kw + (size_t)id * 4096;
    const float* vwb = vw + (size_t)id * 4096;

    for (int i = tid; i < 4096; i += 256) {
        int c = i >> 6, mm = i & 63;
        int sl = mm >> 3, w = mm & 7;
        float xv = x[(((size_t)b*64 + c)*1024 + (s0 + sl))*8 + w];
        xd[c*132 + 2*mm] = xv;
        xd[c*132 + 2*mm + 1] = xv;
        int d2 = i >> 6, c2 = i & 63;
        qT[c2*68 + d2] = qwb[d2*64 + c2];
        kT[c2*68 + d2] = kwb[d2*64 + c2];
        vT[c2*68 + d2] = vwb[d2*64 + c2];
    }
    __syncthreads();

    const int tx = tid & 15, ty = tid >> 4;
    ULL aq[4][2] = {}, ak[4][2] = {}, av[4][2] = {};
    #pragma unroll 2
    for (int c = 0; c < 64; c++) {
        ulonglong2 qp = *(const ulonglong2*)(qT + c*68 + tx*4);
        ulonglong2 kp = *(const ulonglong2*)(kT + c*68 + tx*4);
        ulonglong2 vp = *(const ulonglong2*)(vT + c*68 + tx*4);
        ulonglong2 xa = *(const ulonglong2*)(xd + c*132 + ty*8);
        ulonglong2 xb = *(const ulonglong2*)(xd + c*132 + ty*8 + 4);
        fma2(aq[0][0], xa.x, qp.x); fma2(aq[0][1], xa.x, qp.y);
        fma2(aq[1][0], xa.y, qp.x); fma2(aq[1][1], xa.y, qp.y);
        fma2(aq[2][0], xb.x, qp.x); fma2(aq[2][1], xb.x, qp.y);
        fma2(aq[3][0], xb.y, qp.x); fma2(aq[3][1], xb.y, qp.y);
        fma2(ak[0][0], xa.x, kp.x); fma2(ak[0][1], xa.x, kp.y);
        fma2(ak[1][0], xa.y, kp.x); fma2(ak[1][1], xa.y, kp.y);
        fma2(ak[2][0], xb.x, kp.x); fma2(ak[2][1], xb.x, kp.y);
        fma2(ak[3][0], xb.y, kp.x); fma2(ak[3][1], xb.y, kp.y);
        fma2(av[0][0], xa.x, vp.x); fma2(av[0][1], xa.x, vp.y);
        fma2(av[1][0], xa.y, vp.x); fma2(av[1][1], xa.y, vp.y);
        fma2(av[2][0], xb.x, vp.x); fma2(av[2][1], xb.x, vp.y);
        fma2(av[3][0], xb.y, vp.x); fma2(av[3][1], xb.y, vp.y);
    }

    float sv[4];
    #pragma unroll
    for (int j = 0; j < 4; j++) sv[j] = g_svec[tx*4 + j];
    const float SC = 0.08838834764831845f;   // 1/sqrt(128)

    #pragma unroll
    for (int i = 0; i < 4; i++) {
        int mm = ty*4 + i;
        int sl = mm >> 3, w = mm & 7;
        int h = w >> 1;
        int jb = ((w & 1) << 6) + tx*4;
        int s = s0 + sl;
        int bh = b*4 + h;
        size_t base = ((size_t)bh*1024 + s)*128 + jb;
        float2 a0, a1; uint2 u;
        a0 = unpk(aq[i][0]); a1 = unpk(aq[i][1]);
        u.x = bf2pack((a0.x+sv[0])*SC, (a0.y+sv[1])*SC);
        u.y = bf2pack((a1.x+sv[2])*SC, (a1.y+sv[3])*SC);
        *(uint2*)&g_qb[base] = u;
        a0 = unpk(ak[i][0]); a1 = unpk(ak[i][1]);
        u.x = bf2pack(a0.x, a0.y); u.y = bf2pack(a1.x, a1.y);
        *(uint2*)&g_kb[base] = u;
        a0 = unpk(av[i][0]); a1 = unpk(av[i][1]);
        u.x = bf2pack(a0.x, a0.y); u.y = bf2pack(a1.x, a1.y);
        *(uint2*)&g_vb[base] = u;
        *(float4*)&g_v[base] = make_float4(a0.x+sv[0], a0.y+sv[1], a1.x+sv[2], a1.y+sv[3]);
    }
}

// ---------------- K2: partial pv per (chunk, bh) ----------------
__global__ __launch_bounds__(256) void k_pvp() {
    __shared__ float w[128];
    __shared__ float red[256];
    const int g = blockIdx.x, bh = blockIdx.y, tid = threadIdx.x;
    if (tid < 128) w[tid] = g_pw[(size_t)bh*1024 + g*128 + tid];
    __syncthreads();
    const int d = tid & 127, half = tid >> 7;
    const float* vv = g_v + (size_t)bh*131072 + (size_t)g*128*128 + (size_t)half*64*128;
    const float* wp = w + half*64;
    float acc = 0.f;
    #pragma unroll 8
    for (int k = 0; k < 64; k++) acc += wp[k] * vv[(size_t)k*128 + d];
    red[tid] = acc; __syncthreads();
    if (tid < 128)
        g_pvpart[((size_t)bh*8 + g)*128 + d] = red[tid] + red[tid + 128];
}

// ---------------- K3: bf16 mma.sync flash attention, cp.async double-buffered ----------------
#define SQO 0
#define SK0 32768
#define SK1 65536
#define SV0 98304
#define SV1 131072
#define SADD 163840
#define ATTN_SMEM 164864

__global__ __launch_bounds__(256) void k_attn(
    const float* __restrict__ gate, const float* __restrict__ out_w,
    const float* __restrict__ out_b, float* __restrict__ out)
{
    extern __shared__ char smc[];
    float* smf = (float*)smc;
    const uint32_t sb = smem_u32(smc);
    const int stile = blockIdx.x, bh = blockIdx.y;
    const int b = bh >> 2, h = bh & 3;
    const int s0 = stile * 128;
    const int tid = threadIdx.x, wid = tid >> 5, l = tid & 31;
    const int lr = l & 7, lb8 = (l >> 3) & 1, lb16 = l >> 4;

    const float gv  = 1.f / (1.f + __expf(-gate[h]));
    const float omg = 1.f - gv;
    float* sAdd = (float*)(smc + SADD);
    if (tid < 128) {
        float pvs = 0.f;
        #pragma unroll
        for (int gg = 0; gg < 8; gg++) pvs += g_pvpart[((size_t)bh*8 + gg)*128 + tid];
        sAdd[tid] = omg * g_svec[tid & 63] + gv * pvs;
    }

    // ---- stage Q (once) ----
    const __nv_bfloat16* Qb = g_qb + (size_t)bh*131072 + (size_t)s0*128;
    for (int i = tid; i < 2048; i += 256) {
        int r = i >> 4, cc = i & 15;
        *(uint4*)(smc + SQO + r*256 + ((cc ^ (r & 7)) << 4)) =
            *(const uint4*)(Qb + (size_t)r*128 + cc*8);
    }

    const __nv_bfloat16* Kb = g_kb + (size_t)bh*131072;
    const __nv_bfloat16* Vb = g_vb + (size_t)bh*131072;

    // prefetch chunk 0
    {
        const uint32_t kB = sb + SK0, vB = sb + SV0;
        for (int i = tid; i < 2048; i += 256) {
            int r = i >> 4, cc = i & 15;
            uint32_t sw = (uint32_t)(r*256 + ((cc ^ (r & 7)) << 4));
            CP_ASYNC16(kB + sw, Kb + (size_t)r*128 + cc*8);
            CP_ASYNC16(vB + sw, Vb + (size_t)r*128 + cc*8);
        }
        CP_COMMIT();
    }

    // ---- cache Q A-frags ----
    __syncthreads();   // Q visible
    const int mb = wid * 16;
    const int arow = mb + lr + (lb8 << 3);
    const uint32_t aBase = sb + SQO + arow*256;
    uint32_t aq[8][4];
    #pragma unroll
    for (int ks = 0; ks < 8; ks++) {
        uint32_t ad = aBase + (((uint32_t)((ks << 1) | lb16) ^ (uint32_t)lr) << 4);
        LDSM4(aq[ks], ad);
    }

    float oacc[16][4];
    #pragma unroll
    for (int i = 0; i < 16; i++)
        #pragma unroll
        for (int j = 0; j < 4; j++) oacc[i][j] = 0.f;
    float lsum0 = 0.f, lsum1 = 0.f;

    for (int c = 0; c < 8; c++) {
        if (c < 7) {   // prefetch next chunk into other buffer
            const int t0n = (c + 1) * 128;
            const uint32_t kB = sb + (((c + 1) & 1) ? SK1 : SK0);
            const uint32_t vB = sb + (((c + 1) & 1) ? SV1 : SV0);
            for (int i = tid; i < 2048; i += 256) {
                int r = i >> 4, cc = i & 15;
                uint32_t sw = (uint32_t)(r*256 + ((cc ^ (r & 7)) << 4));
                CP_ASYNC16(kB + sw, Kb + (size_t)(t0n + r)*128 + cc*8);
                CP_ASYNC16(vB + sw, Vb + (size_t)(t0n + r)*128 + cc*8);
            }
            CP_COMMIT();
            CP_WAIT1();
        } else {
            CP_WAIT0();
        }
        __syncthreads();   // chunk c data visible to all

        const uint32_t kRowB = sb + ((c & 1) ? SK1 : SK0) + (uint32_t)(lr + (lb16 << 3))*256;
        const uint32_t vRowB = sb + ((c & 1) ? SV1 : SV0) + (uint32_t)(lr + (lb8  << 3))*256;

        // ---- S = Q @ K^T ----
        float sacc[16][4];
        #pragma unroll
        for (int i = 0; i < 16; i++)
            #pragma unroll
            for (int j = 0; j < 4; j++) sacc[i][j] = 0.f;

        #pragma unroll
        for (int ks = 0; ks < 8; ks++) {
            #pragma unroll
            for (int n2 = 0; n2 < 8; n2++) {
                uint32_t bfr[4];
                uint32_t ad = kRowB + (uint32_t)n2*4096
                            + (((uint32_t)((ks << 1) | lb8) ^ (uint32_t)lr) << 4);
                LDSM4(bfr, ad);
                MMA16816(sacc[2*n2],     aq[ks], bfr[0], bfr[1]);
                MMA16816(sacc[2*n2 + 1], aq[ks], bfr[2], bfr[3]);
            }
        }

        // ---- exp (C=0; row-const q·s cancelled analytically) -> P A-frags ----
        uint32_t pf[8][4];
        #pragma unroll
        for (int nt = 0; nt < 16; nt++) {
            float e0 = __expf(sacc[nt][0]);
            float e1 = __expf(sacc[nt][1]);
            float e2 = __expf(sacc[nt][2]);
            float e3 = __expf(sacc[nt][3]);
            lsum0 += e0 + e1;
            lsum1 += e2 + e3;
            pf[nt >> 1][(nt & 1)*2]     = bf2pack(e0, e1);
            pf[nt >> 1][(nt & 1)*2 + 1] = bf2pack(e2, e3);
        }

        // ---- O += P @ V ----
        #pragma unroll
        for (int np = 0; np < 8; np++) {
            #pragma unroll
            for (int ks = 0; ks < 8; ks++) {
                uint32_t bfr[4];
                uint32_t ad = vRowB + (uint32_t)ks*4096
                            + (((uint32_t)((np << 1) | lb16) ^ (uint32_t)lr) << 4);
                LDSM4T(bfr, ad);
                MMA16816(oacc[2*np],     pf[ks], bfr[0], bfr[1]);
                MMA16816(oacc[2*np + 1], pf[ks], bfr[2], bfr[3]);
            }
        }
        __syncthreads();   // buffer reads done before it is re-staged
    }

    // ---- row sums (quad reduce) ----
    lsum0 += __shfl_xor_sync(0xffffffffu, lsum0, 1);
    lsum0 += __shfl_xor_sync(0xffffffffu, lsum0, 2);
    lsum1 += __shfl_xor_sync(0xffffffffu, lsum1, 1);
    lsum1 += __shfl_xor_sync(0xffffffffu, lsum1, 2);
    const float inv0 = omg / lsum0;
    const float inv1 = omg / lsum1;

    float* oT  = smf;              // [128 d][PIT r], col = r ^ (((d>>3)&15)<<2)
    float* owT = smf + 128*PIT;

    const int r0r = mb + (l >> 2), r1r = r0r + 8;
    #pragma unroll
    for (int nt = 0; nt < 16; nt++) {
        int d0 = 8*nt + 2*(l & 3);
        int sw = nt << 2;
        oT[d0*PIT     + (r0r ^ sw)] = oacc[nt][0]*inv0 + sAdd[d0];
        oT[(d0+1)*PIT + (r0r ^ sw)] = oacc[nt][1]*inv0 + sAdd[d0+1];
        oT[d0*PIT     + (r1r ^ sw)] = oacc[nt][2]*inv1 + sAdd[d0];
        oT[(d0+1)*PIT + (r1r ^ sw)] = oacc[nt][3]*inv1 + sAdd[d0+1];
    }
    for (int i = tid; i < 4096; i += 256) {
        int cp = i & 63, cc = i >> 6;
        owT[cp*68 + cc] = out_w[cc*64 + cp];
    }
    __syncthreads();

    // ---- GEMM2: out = oT @ out_w^T + out_b (fp32x2) ----
    const int tx = tid & 15, ty = tid >> 4;
    ULL facp[2][4][4];
    #pragma unroll
    for (int ws = 0; ws < 2; ws++)
        #pragma unroll
        for (int rp = 0; rp < 4; rp++)
            #pragma unroll
            for (int j = 0; j < 4; j++) facp[ws][rp][j] = 0ULL;

    #pragma unroll 2
    for (int cp = 0; cp < 64; cp++) {
        int swz0 = ((cp >> 3) & 15) << 2;
        int swz1 = (((cp + 64) >> 3) & 15) << 2;
        const float* r0 = oT + cp*PIT;
        const float* r1 = oT + (cp + 64)*PIT;
        ulonglong2 oa = { *(const ULL*)(r0 + ((ty*8) ^ swz0)),
                          *(const ULL*)(r0 + ((ty*8 + 2) ^ swz0)) };
        ulonglong2 ob = { *(const ULL*)(r0 + ((ty*8 + 4) ^ swz0)),
                          *(const ULL*)(r0 + ((ty*8 + 6) ^ swz0)) };
        ulonglong2 oc = { *(const ULL*)(r1 + ((ty*8) ^ swz1)),
                          *(const ULL*)(r1 + ((ty*8 + 2) ^ swz1)) };
        ulonglong2 od = { *(const ULL*)(r1 + ((ty*8 + 4) ^ swz1)),
                          *(const ULL*)(r1 + ((ty*8 + 6) ^ swz1)) };
        float4 wf = *(const float4*)&owT[cp*68 + tx*4];
        ULL wd[4] = {dup2(wf.x), dup2(wf.y), dup2(wf.z), dup2(wf.w)};
        #pragma unroll
        for (int j = 0; j < 4; j++) {
            fma2(facp[0][0][j], oa.x, wd[j]);
            fma2(facp[0][1][j], oa.y, wd[j]);
            fma2(facp[0][2][j], ob.x, wd[j]);
            fma2(facp[0][3][j], ob.y, wd[j]);
            fma2(facp[1][0][j], oc.x, wd[j]);
            fma2(facp[1][1][j], oc.y, wd[j]);
            fma2(facp[1][2][j], od.x, wd[j]);
            fma2(facp[1][3][j], od.y, wd[j]);
        }
    }

    float ob4[4];
    #pragma unroll
    for (int j = 0; j < 4; j++) ob4[j] = out_b[tx*4 + j];

    #pragma unroll
    for (int ws = 0; ws < 2; ws++) {
        int w = h*2 + ws;
        #pragma unroll
        for (int rp = 0; rp < 4; rp++) {
            float2 f0 = unpk(facp[ws][rp][0]);
            float2 f1 = unpk(facp[ws][rp][1]);
            float2 f2 = unpk(facp[ws][rp][2]);
            float2 f3 = unpk(facp[ws][rp][3]);
            int sA = s0 + ty*8 + 2*rp;
            float4 lo = {f0.x+ob4[0], f1.x+ob4[1], f2.x+ob4[2], f3.x+ob4[3]};
            float4 hi = {f0.y+ob4[0], f1.y+ob4[1], f2.y+ob4[2], f3.y+ob4[3]};
            *(float4*)&out[(((size_t)b*1024 + sA    )*8 + w)*64 + tx*4] = lo;
            *(float4*)&out[(((size_t)b*1024 + sA + 1)*8 + w)*64 + tx*4] = hi;
        }
    }
}

// ---------------- launch ----------------
extern "C" void kernel_launch(void* const* d_in, const int* in_sizes, int n_in,
                              void* d_out, int out_size) {
    const float* x        = (const float*)d_in[0];
    const float* pos      = (const float*)d_in[1];
    const float* strength = (const float*)d_in[2];
    const int*   embid    = (const int*)  d_in[3];
    const float* qw       = (const float*)d_in[4];
    const float* kw       = (const float*)d_in[5];
    const float* vw       = (const float*)d_in[6];
    const float* pw1      = (const float*)d_in[7];
    const float* pb1      = (const float*)d_in[8];
    const float* pw2      = (const float*)d_in[9];
    const float* pb2      = (const float*)d_in[10];
    const float* hw       = (const float*)d_in[11];
    // d_in[12] = head_b (cancels in softmax)
    const float* gate     = (const float*)d_in[13];
    const float* ow       = (const float*)d_in[14];
    const float* ob       = (const float*)d_in[15];
    const float* sw       = (const float*)d_in[16];
    const float* sb       = (const float*)d_in[17];
    float* out = (float*)d_out;

    cudaFuncSetAttribute(k_proj, cudaFuncAttributeMaxDynamicSharedMemorySize, 86016);
    cudaFuncSetAttribute(k_attn, cudaFuncAttributeMaxDynamicSharedMemorySize, ATTN_SMEM);

    k_posb1<<<17, 512>>>(pos, pw1, pb1, pw2, pb2, hw, strength, sw, sb);
    k_proj<<<dim3(128, 4), 256, 86016>>>(x, qw, kw, vw, embid);
    k_pvp<<<dim3(8, 16), 256>>>();
    k_attn<<<dim3(8, 16), 256, ATTN_SMEM>>>(gate, ow, ob, out);
}